// round 1
// baseline (speedup 1.0000x reference)
#include <cuda_runtime.h>

// Shapes (fixed for this problem instance)
#define BB 256      // batch
#define SS 512      // encoder sequence length
#define FF 64       // feature dim
#define HH 1024     // hidden dim

#define NCTA 128    // 4 batch-blocks x 32 hidden-blocks (all co-resident on 148 SMs)
#define NTHR 256
#define MB 64       // batch rows per CTA tile
#define NH 32       // hidden cols per CTA tile
#define GT 128      // gate cols per tile = 4 * NH  (i,f,g,o)
#define KB 16       // K chunk
#define KTOT (HH + FF)

// Persistent state (no allocations allowed)
__device__ float g_h[2][BB * HH];
__device__ float g_c[BB * HH];
__device__ float g_x[BB * FF];
__device__ unsigned g_bar_cnt;
__device__ unsigned g_bar_gen;

struct __align__(16) Smem {
    float As[KB][MB + 4];   // K-major staged A (h / x) tile, padded
    float Bs[KB][GT + 4];   // K-major staged W tile, padded
    union {
        float Gs[GT][MB + 1];  // gate tile for pointwise phase
        float Hs[2][HH];       // h rows for prediction phase
    };
};

__device__ __forceinline__ void grid_barrier() {
    __syncthreads();
    if (threadIdx.x == 0) {
        __threadfence();
        unsigned gen = *(volatile unsigned*)&g_bar_gen;
        if (atomicAdd(&g_bar_cnt, 1u) == NCTA - 1u) {
            atomicExch(&g_bar_cnt, 0u);
            __threadfence();
            atomicAdd(&g_bar_gen, 1u);
        } else {
            while (*(volatile unsigned*)&g_bar_gen == gen) { }
        }
        __threadfence();
    }
    __syncthreads();
}

__device__ __forceinline__ float sigm(float x) {
    return 1.0f / (1.0f + __expf(-x));
}
__device__ __forceinline__ float tanh_f(float x) {
    float xx = fminf(fmaxf(x, -15.0f), 15.0f);
    float e = __expf(2.0f * xx);
    return (e - 1.0f) / (e + 1.0f);
}
__device__ __forceinline__ float4 ldg4(const float* p) {
    return *(const float4*)p;
}

// One LSTM step for this CTA's (MB x NH) tile.
// gates[b, 4H] = h @ Whh^T + x @ Wih^T + (bih + bhh); then pointwise update.
__device__ __forceinline__ void lstm_step(
    Smem& sm,
    const float* __restrict__ hcur, float* __restrict__ hnext, float* __restrict__ cbuf,
    const float* __restrict__ Whh, const float* __restrict__ Wih,
    const float* __restrict__ bih, const float* __restrict__ bhh,
    const float* __restrict__ xptr, int xstride,
    int m0, int n0)
{
    const int tid = threadIdx.x;
    const int tx = tid & 15, ty = tid >> 4;
    const int r0 = ty * 4, c0 = tx * 8;

    // A loader: one float4 per thread per chunk (64 rows x 4 float4)
    const int arow = tid >> 2, ac4 = tid & 3;
    // B loader: two float4 per thread per chunk (128 rows x 4 float4)
    const int brow0 = tid >> 2;          // rows 0..63
    const int brow1 = brow0 + 64;        // rows 64..127
    const int bc4 = tid & 3;

    const int g0 = brow0 >> 5, h0i = n0 + (brow0 & 31);
    const int g1 = brow1 >> 5, h1i = n0 + (brow1 & 31);
    const float* whh_r0 = Whh + (size_t)(g0 * HH + h0i) * HH;
    const float* whh_r1 = Whh + (size_t)(g1 * HH + h1i) * HH;
    const float* wih_r0 = Wih + (size_t)(g0 * HH + h0i) * FF;
    const float* wih_r1 = Wih + (size_t)(g1 * HH + h1i) * FF;
    const float* ha = hcur + (size_t)(m0 + arow) * HH;
    const float* xa = xptr + (size_t)(m0 + arow) * xstride;

    float acc[4][8];
#pragma unroll
    for (int i = 0; i < 4; i++)
#pragma unroll
        for (int j = 0; j < 8; j++) acc[i][j] = 0.0f;

    float4 av, bv0, bv1;
    // prefetch chunk 0
    av  = ldg4(ha + 0 + ac4 * 4);
    bv0 = ldg4(whh_r0 + 0 + bc4 * 4);
    bv1 = ldg4(whh_r1 + 0 + bc4 * 4);

    for (int kc = 0; kc < KTOT; kc += KB) {
        __syncthreads();   // previous compute done, smem reusable
        // store staged registers (transposed to K-major)
        sm.As[ac4 * 4 + 0][arow] = av.x;
        sm.As[ac4 * 4 + 1][arow] = av.y;
        sm.As[ac4 * 4 + 2][arow] = av.z;
        sm.As[ac4 * 4 + 3][arow] = av.w;
        sm.Bs[bc4 * 4 + 0][brow0] = bv0.x;
        sm.Bs[bc4 * 4 + 1][brow0] = bv0.y;
        sm.Bs[bc4 * 4 + 2][brow0] = bv0.z;
        sm.Bs[bc4 * 4 + 3][brow0] = bv0.w;
        sm.Bs[bc4 * 4 + 0][brow1] = bv1.x;
        sm.Bs[bc4 * 4 + 1][brow1] = bv1.y;
        sm.Bs[bc4 * 4 + 2][brow1] = bv1.z;
        sm.Bs[bc4 * 4 + 3][brow1] = bv1.w;
        __syncthreads();

        // prefetch next chunk (hidden under compute)
        int kn = kc + KB;
        if (kn < KTOT) {
            if (kn < HH) {
                av  = ldg4(ha + kn + ac4 * 4);
                bv0 = ldg4(whh_r0 + kn + bc4 * 4);
                bv1 = ldg4(whh_r1 + kn + bc4 * 4);
            } else {
                int kk = kn - HH;
                av  = ldg4(xa + kk + ac4 * 4);
                bv0 = ldg4(wih_r0 + kk + bc4 * 4);
                bv1 = ldg4(wih_r1 + kk + bc4 * 4);
            }
        }

        // compute this chunk
#pragma unroll
        for (int k = 0; k < KB; k++) {
            float4 a  = *(const float4*)&sm.As[k][r0];
            float4 b0 = *(const float4*)&sm.Bs[k][c0];
            float4 b1 = *(const float4*)&sm.Bs[k][c0 + 4];
            float ar[4] = {a.x, a.y, a.z, a.w};
            float br[8] = {b0.x, b0.y, b0.z, b0.w, b1.x, b1.y, b1.z, b1.w};
#pragma unroll
            for (int i = 0; i < 4; i++)
#pragma unroll
                for (int j = 0; j < 8; j++)
                    acc[i][j] = fmaf(ar[i], br[j], acc[i][j]);
        }
    }

    // epilogue: bias add, write gate tile to smem
    __syncthreads();
#pragma unroll
    for (int j = 0; j < 8; j++) {
        int c = c0 + j;
        int gg = c >> 5;
        int hid = n0 + (c & 31);
        float bias = bih[gg * HH + hid] + bhh[gg * HH + hid];
#pragma unroll
        for (int i = 0; i < 4; i++)
            sm.Gs[c][r0 + i] = acc[i][j] + bias;
    }
    __syncthreads();

    // pointwise LSTM update (owner-exclusive c, ping-pong h)
    for (int e = tid; e < MB * NH; e += NTHR) {
        int r = e >> 5;
        int hid = e & 31;
        float iv = sm.Gs[hid][r];
        float fv = sm.Gs[32 + hid][r];
        float gv = sm.Gs[64 + hid][r];
        float ov = sm.Gs[96 + hid][r];
        int gi = (m0 + r) * HH + n0 + hid;
        float cold = cbuf[gi];
        float cn = sigm(fv) * cold + sigm(iv) * tanh_f(gv);
        float hn = sigm(ov) * tanh_f(cn);
        cbuf[gi] = cn;
        hnext[gi] = hn;
    }
}

// pred = h @ W_fc^T + b_fc ; write to out[b, t, :] and g_x.
// Each CTA owns 2 batch rows x 64 output features.
__device__ __forceinline__ void pred_step(
    Smem& sm, const float* __restrict__ h,
    const float* __restrict__ Wfc, const float* __restrict__ bfc,
    float* __restrict__ out, int t, int T)
{
    const int tid = threadIdx.x;
    const int pr0 = blockIdx.x * 2;

    // stage the 2 h rows into smem (512 float4s, 2 per thread)
#pragma unroll
    for (int q = 0; q < 2; q++) {
        int f4 = tid + q * 256;
        int r = f4 >> 8;
        int c4 = f4 & 255;
        *(float4*)&sm.Hs[r][c4 * 4] = ldg4(&h[(size_t)(pr0 + r) * HH + c4 * 4]);
    }
    __syncthreads();

    const int warp = tid >> 5, lane = tid & 31;
    for (int oi = warp; oi < 128; oi += 8) {
        int r = oi >> 6;
        int f = oi & 63;
        const float4* wrow = (const float4*)&Wfc[(size_t)f * HH];
        const float4* hrow = (const float4*)&sm.Hs[r][0];
        float s = 0.0f;
#pragma unroll 4
        for (int k4 = lane; k4 < 256; k4 += 32) {
            float4 w = wrow[k4];
            float4 hv = hrow[k4];
            s += w.x * hv.x + w.y * hv.y + w.z * hv.z + w.w * hv.w;
        }
#pragma unroll
        for (int off = 16; off; off >>= 1)
            s += __shfl_xor_sync(0xffffffffu, s, off);
        if (lane == 0) {
            float p = s + bfc[f];
            int b = pr0 + r;
            out[(size_t)b * T * FF + t * FF + f] = p;
            g_x[b * FF + f] = p;
        }
    }
    __syncthreads();
}

__global__ void __launch_bounds__(NTHR) s2s_kernel(
    const float* __restrict__ x_seq,
    const float* __restrict__ Wih_e, const float* __restrict__ Whh_e,
    const float* __restrict__ bih_e, const float* __restrict__ bhh_e,
    const float* __restrict__ Wih_d, const float* __restrict__ Whh_d,
    const float* __restrict__ bih_d, const float* __restrict__ bhh_d,
    const float* __restrict__ Wfc, const float* __restrict__ bfc,
    const int* __restrict__ plen,
    float* __restrict__ out)
{
    __shared__ Smem sm;
    const int tid = threadIdx.x;
    const int m0 = (blockIdx.x >> 5) * MB;
    const int n0 = (blockIdx.x & 31) * NH;

    // init h0 = c0 = 0 for this CTA's owned region
    for (int e = tid; e < MB * NH; e += NTHR) {
        int r = e >> 5;
        int hid = e & 31;
        int gi = (m0 + r) * HH + n0 + hid;
        g_h[0][gi] = 0.0f;
        g_c[gi] = 0.0f;
    }
    grid_barrier();

    int cur = 0;
    // ---- encoder: 512 steps ----
    for (int t = 0; t < SS; t++) {
        lstm_step(sm, g_h[cur], g_h[cur ^ 1], g_c,
                  Whh_e, Wih_e, bih_e, bhh_e,
                  x_seq + (size_t)t * FF, SS * FF, m0, n0);
        grid_barrier();
        cur ^= 1;
    }

    // ---- decoder ----
    const int T = *plen;
    for (int t = 0; t < T; t++) {
        const float* xp = (t == 0) ? (x_seq + (size_t)(SS - 1) * FF) : g_x;
        const int xs = (t == 0) ? (SS * FF) : FF;
        lstm_step(sm, g_h[cur], g_h[cur ^ 1], g_c,
                  Whh_d, Wih_d, bih_d, bhh_d, xp, xs, m0, n0);
        grid_barrier();
        cur ^= 1;
        pred_step(sm, g_h[cur], Wfc, bfc, out, t, T);
        grid_barrier();
    }
}

extern "C" void kernel_launch(void* const* d_in, const int* in_sizes, int n_in,
                              void* d_out, int out_size)
{
    const float* x_seq = (const float*)d_in[0];
    const float* Wih_e = (const float*)d_in[1];
    const float* Whh_e = (const float*)d_in[2];
    const float* bih_e = (const float*)d_in[3];
    const float* bhh_e = (const float*)d_in[4];
    const float* Wih_d = (const float*)d_in[5];
    const float* Whh_d = (const float*)d_in[6];
    const float* bih_d = (const float*)d_in[7];
    const float* bhh_d = (const float*)d_in[8];
    const float* Wfc   = (const float*)d_in[9];
    const float* bfc   = (const float*)d_in[10];
    const int*   plen  = (const int*)d_in[11];
    float* out = (float*)d_out;

    s2s_kernel<<<NCTA, NTHR>>>(x_seq, Wih_e, Whh_e, bih_e, bhh_e,
                               Wih_d, Whh_d, bih_d, bhh_d,
                               Wfc, bfc, plen, out);
}

// round 3
// speedup vs baseline: 2.9799x; 2.9799x over previous
#include <cuda_runtime.h>
#include <cstdint>

// Shapes (fixed for this problem instance)
#define BB 256      // batch
#define SS 512      // encoder sequence length
#define FF 64      // feature dim
#define HH 1024     // hidden dim

#define NCTA 128    // 4 batch-blocks x 32 hidden-blocks (all co-resident)
#define NTHR 256
#define MB 64       // batch rows per CTA tile
#define NH 32       // hidden cols per CTA tile
#define GT 128      // gate cols per tile = 4 * NH  (i,f,g,o)
#define KC 16       // K chunk (two k8 mma sub-steps)
#define KTOT (HH + FF)
#define NCHUNK (KTOT / KC)   // 68
#define AST 20      // As row stride in floats (pad 4 -> conflict-free ldmatrix)
#define BST 20
#define GST 130

// Persistent state (no allocations allowed)
__device__ float g_h[2][BB * HH];
__device__ float g_c[BB * HH];
__device__ float g_x[BB * FF];
__device__ unsigned g_bar_cnt;
__device__ unsigned g_bar_gen;

struct Stage {
    float As[MB][AST];
    float Bs[GT][BST];
};

// Staging tiles overlap the gate/pred buffers (used in disjoint phases).
// __align__(16) is load-bearing: float4 accesses + ldmatrix require it.
union __align__(16) SmemU {
    Stage st[2];           // double-buffered staging
    float Gs[MB][GST];     // gates, row-major [batch][4*NH]
    float Hs[2][HH];       // h rows for prediction phase
};

__device__ __forceinline__ void grid_barrier() {
    __syncthreads();
    if (threadIdx.x == 0) {
        __threadfence();
        unsigned gen = *(volatile unsigned*)&g_bar_gen;
        if (atomicAdd(&g_bar_cnt, 1u) == NCTA - 1u) {
            atomicExch(&g_bar_cnt, 0u);
            __threadfence();
            atomicAdd(&g_bar_gen, 1u);
        } else {
            while (*(volatile unsigned*)&g_bar_gen == gen) { }
        }
        __threadfence();
    }
    __syncthreads();
}

__device__ __forceinline__ float sigm(float x) {
    return 1.0f / (1.0f + __expf(-x));
}
__device__ __forceinline__ float tanh_f(float x) {
    float xx = fminf(fmaxf(x, -15.0f), 15.0f);
    float e = __expf(2.0f * xx);
    return (e - 1.0f) / (e + 1.0f);
}
__device__ __forceinline__ float4 ldg4(const float* p) {
    return *(const float4*)p;
}
__device__ __forceinline__ float tf32r(float x) {
    uint32_t r;
    asm("cvt.rna.tf32.f32 %0, %1;" : "=r"(r) : "f"(x));
    return __uint_as_float(r);
}
__device__ __forceinline__ void ldsm4(uint32_t r[4], uint32_t a) {
    asm volatile("ldmatrix.sync.aligned.m8n8.x4.shared.b16 {%0,%1,%2,%3}, [%4];"
                 : "=r"(r[0]), "=r"(r[1]), "=r"(r[2]), "=r"(r[3]) : "r"(a));
}
__device__ __forceinline__ void mmaT(float d[4], const uint32_t a[4],
                                     uint32_t b0, uint32_t b1) {
    asm volatile("mma.sync.aligned.m16n8k8.row.col.f32.tf32.tf32.f32 "
                 "{%0,%1,%2,%3},{%4,%5,%6,%7},{%8,%9},{%0,%1,%2,%3};"
                 : "+f"(d[0]), "+f"(d[1]), "+f"(d[2]), "+f"(d[3])
                 : "r"(a[0]), "r"(a[1]), "r"(a[2]), "r"(a[3]),
                   "r"(b0), "r"(b1));
}

// One LSTM step for this CTA's (MB x NH) tile using tf32 tensor-core mma.
__device__ __forceinline__ void lstm_step(
    SmemU& sm,
    const float* __restrict__ hcur, float* __restrict__ hnext, float* __restrict__ cbuf,
    const float* __restrict__ Whh, const float* __restrict__ Wih,
    const float* __restrict__ bih, const float* __restrict__ bhh,
    const float* __restrict__ xptr, int xstride,
    int m0, int n0)
{
    const int tid = threadIdx.x;
    const int lane = tid & 31, warp = tid >> 5;
    const int wm = (warp & 1) * 32;      // warp m offset within CTA tile
    const int wn = (warp >> 1) * 32;     // warp gate-col offset

    // Staging loaders (row-major, k contiguous -> direct copy, no transpose)
    const int arow = tid >> 2, ac4 = tid & 3;          // A: 64 rows x 4 float4
    const int brow0 = tid >> 2, brow1 = brow0 + 64;    // B: 128 rows x 4 float4
    const int bc4 = tid & 3;

    const int g0 = brow0 >> 5, h0i = n0 + (brow0 & 31);
    const int g1 = brow1 >> 5, h1i = n0 + (brow1 & 31);
    const float* whh_r0 = Whh + (size_t)(g0 * HH + h0i) * HH;
    const float* whh_r1 = Whh + (size_t)(g1 * HH + h1i) * HH;
    const float* wih_r0 = Wih + (size_t)(g0 * HH + h0i) * FF;
    const float* wih_r1 = Wih + (size_t)(g1 * HH + h1i) * FF;
    const float* ha = hcur + (size_t)(m0 + arow) * HH;
    const float* xa = xptr + (size_t)(m0 + arow) * xstride;

    // ldmatrix per-lane row addresses (lane L: tile=L>>3 row=L&7)
    uint32_t sa = (uint32_t)__cvta_generic_to_shared(&sm.st[0].As[0][0]);
    uint32_t sb = (uint32_t)__cvta_generic_to_shared(&sm.st[0].Bs[0][0]);
    const int lr = lane & 7, lt = lane >> 3;
    const int madd = (lt & 1) * 8;      // tiles 1,3: +8 rows
    const int kadd = (lt >> 1) * 4;     // tiles 2,3: +4 k
    uint32_t aA0 = sa + (uint32_t)(((wm + lr + madd) * AST + kadd) << 2);
    uint32_t aA1 = aA0 + (uint32_t)((16 * AST) << 2);
    uint32_t aB0 = sb + (uint32_t)(((wn + lr + madd) * BST + kadd) << 2);
    uint32_t aB1 = aB0 + (uint32_t)((16 * BST) << 2);
    const uint32_t stg = (uint32_t)sizeof(Stage);

    float acc[2][4][4];
#pragma unroll
    for (int mi = 0; mi < 2; mi++)
#pragma unroll
        for (int ni = 0; ni < 4; ni++)
#pragma unroll
            for (int q = 0; q < 4; q++) acc[mi][ni][q] = 0.0f;

    float4 av, bv0, bv1;

    // loader for chunk index ci (k0 = ci*KC)
    auto load_chunk = [&](int ci) {
        int k0 = ci * KC;
        if (k0 < HH) {
            av  = ldg4(ha + k0 + ac4 * 4);
            bv0 = ldg4(whh_r0 + k0 + bc4 * 4);
            bv1 = ldg4(whh_r1 + k0 + bc4 * 4);
        } else {
            int kk = k0 - HH;
            av  = ldg4(xa + kk + ac4 * 4);
            bv0 = ldg4(wih_r0 + kk + bc4 * 4);
            bv1 = ldg4(wih_r1 + kk + bc4 * 4);
        }
    };
    auto store_stage = [&](int s) {
        Stage& st = sm.st[s];
        float4 t;
        t.x = tf32r(av.x);  t.y = tf32r(av.y);  t.z = tf32r(av.z);  t.w = tf32r(av.w);
        *(float4*)&st.As[arow][ac4 * 4] = t;
        t.x = tf32r(bv0.x); t.y = tf32r(bv0.y); t.z = tf32r(bv0.z); t.w = tf32r(bv0.w);
        *(float4*)&st.Bs[brow0][bc4 * 4] = t;
        t.x = tf32r(bv1.x); t.y = tf32r(bv1.y); t.z = tf32r(bv1.z); t.w = tf32r(bv1.w);
        *(float4*)&st.Bs[brow1][bc4 * 4] = t;
    };

    // prologue: chunk0 staged, chunk1 in regs
    load_chunk(0);
    store_stage(0);
    load_chunk(1);

    for (int i = 0; i < NCHUNK; i++) {
        // One barrier per chunk: makes buf[i&1] stores visible AND guarantees
        // prior-parity readers (iter i-1) are done before we overwrite buf[(i+1)&1].
        __syncthreads();
        if (i + 1 < NCHUNK) {
            store_stage((i + 1) & 1);
            if (i + 2 < NCHUNK) load_chunk(i + 2);
        }

        const uint32_t so = (uint32_t)(i & 1) * stg;
        // two k8 sub-steps on buf[i&1]
#pragma unroll
        for (int kb2 = 0; kb2 < 2; kb2++) {
            uint32_t A0[4], A1[4], B0[4], B1[4];
            ldsm4(A0, aA0 + so + kb2 * 32);
            ldsm4(A1, aA1 + so + kb2 * 32);
            ldsm4(B0, aB0 + so + kb2 * 32);
            ldsm4(B1, aB1 + so + kb2 * 32);
            mmaT(acc[0][0], A0, B0[0], B0[2]);
            mmaT(acc[0][1], A0, B0[1], B0[3]);
            mmaT(acc[0][2], A0, B1[0], B1[2]);
            mmaT(acc[0][3], A0, B1[1], B1[3]);
            mmaT(acc[1][0], A1, B0[0], B0[2]);
            mmaT(acc[1][1], A1, B0[1], B0[3]);
            mmaT(acc[1][2], A1, B1[0], B1[2]);
            mmaT(acc[1][3], A1, B1[1], B1[3]);
        }
    }

    // epilogue: spill accumulators to Gs (row-major [batch][gatecol])
    __syncthreads();
#pragma unroll
    for (int mi = 0; mi < 2; mi++)
#pragma unroll
        for (int ni = 0; ni < 4; ni++) {
            int r = wm + mi * 16 + (lane >> 2);
            int c = wn + ni * 8 + (lane & 3) * 2;
            *(float2*)&sm.Gs[r][c]     = make_float2(acc[mi][ni][0], acc[mi][ni][1]);
            *(float2*)&sm.Gs[r + 8][c] = make_float2(acc[mi][ni][2], acc[mi][ni][3]);
        }
    __syncthreads();

    // pointwise LSTM update; hid constant per thread -> hoist biases
    const int hid = tid & 31;
    const int rb = tid >> 5;
    const float bi = bih[0 * HH + n0 + hid] + bhh[0 * HH + n0 + hid];
    const float bf = bih[1 * HH + n0 + hid] + bhh[1 * HH + n0 + hid];
    const float bg = bih[2 * HH + n0 + hid] + bhh[2 * HH + n0 + hid];
    const float bo = bih[3 * HH + n0 + hid] + bhh[3 * HH + n0 + hid];
#pragma unroll
    for (int it = 0; it < (MB * NH) / NTHR; it++) {
        int r = rb + it * 8;
        float iv = sm.Gs[r][hid]      + bi;
        float fv = sm.Gs[r][32 + hid] + bf;
        float gv = sm.Gs[r][64 + hid] + bg;
        float ov = sm.Gs[r][96 + hid] + bo;
        int gi = (m0 + r) * HH + n0 + hid;
        float cold = cbuf[gi];
        float cn = sigm(fv) * cold + sigm(iv) * tanh_f(gv);
        float hn = sigm(ov) * tanh_f(cn);
        cbuf[gi] = cn;
        hnext[gi] = hn;
    }
}

// pred = h @ W_fc^T + b_fc ; write to out[b, t, :] and g_x.
__device__ __forceinline__ void pred_step(
    SmemU& sm, const float* __restrict__ h,
    const float* __restrict__ Wfc, const float* __restrict__ bfc,
    float* __restrict__ out, int t, int T)
{
    const int tid = threadIdx.x;
    const int pr0 = blockIdx.x * 2;

#pragma unroll
    for (int q = 0; q < 2; q++) {
        int f4 = tid + q * 256;
        int r = f4 >> 8;
        int c4 = f4 & 255;
        *(float4*)&sm.Hs[r][c4 * 4] = ldg4(&h[(size_t)(pr0 + r) * HH + c4 * 4]);
    }
    __syncthreads();

    const int warp = tid >> 5, lane = tid & 31;
    for (int oi = warp; oi < 128; oi += 8) {
        int r = oi >> 6;
        int f = oi & 63;
        const float4* wrow = (const float4*)&Wfc[(size_t)f * HH];
        const float4* hrow = (const float4*)&sm.Hs[r][0];
        float s = 0.0f;
#pragma unroll 4
        for (int k4 = lane; k4 < 256; k4 += 32) {
            float4 w = wrow[k4];
            float4 hv = hrow[k4];
            s += w.x * hv.x + w.y * hv.y + w.z * hv.z + w.w * hv.w;
        }
#pragma unroll
        for (int off = 16; off; off >>= 1)
            s += __shfl_xor_sync(0xffffffffu, s, off);
        if (lane == 0) {
            float p = s + bfc[f];
            int b = pr0 + r;
            out[(size_t)b * T * FF + t * FF + f] = p;
            g_x[b * FF + f] = p;
        }
    }
    __syncthreads();
}

__global__ void __launch_bounds__(NTHR) s2s_kernel(
    const float* __restrict__ x_seq,
    const float* __restrict__ Wih_e, const float* __restrict__ Whh_e,
    const float* __restrict__ bih_e, const float* __restrict__ bhh_e,
    const float* __restrict__ Wih_d, const float* __restrict__ Whh_d,
    const float* __restrict__ bih_d, const float* __restrict__ bhh_d,
    const float* __restrict__ Wfc, const float* __restrict__ bfc,
    const int* __restrict__ plen,
    float* __restrict__ out)
{
    __shared__ SmemU sm;
    const int tid = threadIdx.x;
    const int m0 = (blockIdx.x >> 5) * MB;
    const int n0 = (blockIdx.x & 31) * NH;

    // init h0 = c0 = 0 for this CTA's owned region
    for (int e = tid; e < MB * NH; e += NTHR) {
        int r = e >> 5;
        int hid = e & 31;
        int gi = (m0 + r) * HH + n0 + hid;
        g_h[0][gi] = 0.0f;
        g_c[gi] = 0.0f;
    }
    grid_barrier();

    int cur = 0;
    // ---- encoder: 512 steps ----
    for (int t = 0; t < SS; t++) {
        lstm_step(sm, g_h[cur], g_h[cur ^ 1], g_c,
                  Whh_e, Wih_e, bih_e, bhh_e,
                  x_seq + (size_t)t * FF, SS * FF, m0, n0);
        grid_barrier();
        cur ^= 1;
    }

    // ---- decoder ----
    const int T = *plen;
    for (int t = 0; t < T; t++) {
        const float* xp = (t == 0) ? (x_seq + (size_t)(SS - 1) * FF) : g_x;
        const int xs = (t == 0) ? (SS * FF) : FF;
        lstm_step(sm, g_h[cur], g_h[cur ^ 1], g_c,
                  Whh_d, Wih_d, bih_d, bhh_d, xp, xs, m0, n0);
        grid_barrier();
        cur ^= 1;
        pred_step(sm, g_h[cur], Wfc, bfc, out, t, T);
        grid_barrier();
    }
}

extern "C" void kernel_launch(void* const* d_in, const int* in_sizes, int n_in,
                              void* d_out, int out_size)
{
    const float* x_seq = (const float*)d_in[0];
    const float* Wih_e = (const float*)d_in[1];
    const float* Whh_e = (const float*)d_in[2];
    const float* bih_e = (const float*)d_in[3];
    const float* bhh_e = (const float*)d_in[4];
    const float* Wih_d = (const float*)d_in[5];
    const float* Whh_d = (const float*)d_in[6];
    const float* bih_d = (const float*)d_in[7];
    const float* bhh_d = (const float*)d_in[8];
    const float* Wfc   = (const float*)d_in[9];
    const float* bfc   = (const float*)d_in[10];
    const int*   plen  = (const int*)d_in[11];
    float* out = (float*)d_out;

    s2s_kernel<<<NCTA, NTHR>>>(x_seq, Wih_e, Whh_e, bih_e, bhh_e,
                               Wih_d, Whh_d, bih_d, bhh_d,
                               Wfc, bfc, plen, out);
}

// round 4
// speedup vs baseline: 3.5898x; 1.2047x over previous
#include <cuda_runtime.h>
#include <cstdint>

// Shapes (fixed for this problem instance)
#define BB 256      // batch
#define SS 512      // encoder sequence length
#define FF 64       // feature dim
#define HH 1024     // hidden dim

#define NCTA 128    // 4 batch-blocks x 32 hidden-blocks (all co-resident)
#define NTHR 256
#define MB 64       // batch rows per CTA tile
#define NH 32       // hidden cols per CTA tile
#define GT 128      // gate cols per tile = 4 * NH  (i,f,g,o)
#define KC 32       // K chunk (four k8 mma sub-steps)
#define KTOT (HH + FF)
#define NCHUNK (KTOT / KC)   // 34
#define AST 36      // As row stride in floats (4r mod 32 distinct -> ldsm conflict-free)
#define BST 36
#define GST 130
#define NSTG 4      // cp.async pipeline depth

// Persistent state (no allocations allowed)
__device__ float g_h[2][BB * HH];
__device__ float g_c[BB * HH];
__device__ float g_x[BB * FF];
// tf32-preconverted copies (filled at kernel start each launch)
__device__ float g_whh_e[4 * HH * HH];
__device__ float g_wih_e[4 * HH * FF];
__device__ float g_whh_d[4 * HH * HH];
__device__ float g_wih_d[4 * HH * FF];
__device__ float g_xs[BB * SS * FF];
__device__ unsigned g_bar_cnt;
__device__ unsigned g_bar_gen;

struct Stage {
    float As[MB][AST];
    float Bs[GT][BST];
};
#define STG_BYTES ((int)sizeof(Stage))          // 27648
#define SMEM_BYTES (NSTG * STG_BYTES)           // 110592 (> Gs 33.3KB, > Hs 8KB)

__device__ __forceinline__ void grid_barrier() {
    __syncthreads();
    if (threadIdx.x == 0) {
        __threadfence();
        unsigned gen = *(volatile unsigned*)&g_bar_gen;
        if (atomicAdd(&g_bar_cnt, 1u) == NCTA - 1u) {
            atomicExch(&g_bar_cnt, 0u);
            __threadfence();
            atomicAdd(&g_bar_gen, 1u);
        } else {
            while (*(volatile unsigned*)&g_bar_gen == gen) { }
        }
        __threadfence();
    }
    __syncthreads();
}

__device__ __forceinline__ float sigm(float x) {
    return 1.0f / (1.0f + __expf(-x));
}
__device__ __forceinline__ float tanh_f(float x) {
    float xx = fminf(fmaxf(x, -15.0f), 15.0f);
    float e = __expf(2.0f * xx);
    return (e - 1.0f) / (e + 1.0f);
}
__device__ __forceinline__ float4 ldg4(const float* p) {
    return *(const float4*)p;
}
__device__ __forceinline__ float tf32r(float x) {
    uint32_t r;
    asm("cvt.rna.tf32.f32 %0, %1;" : "=r"(r) : "f"(x));
    return __uint_as_float(r);
}
__device__ __forceinline__ void cpa16(uint32_t s, const float* g) {
    asm volatile("cp.async.cg.shared.global [%0], [%1], 16;" :: "r"(s), "l"(g));
}
__device__ __forceinline__ void ldsm4(uint32_t r[4], uint32_t a) {
    asm volatile("ldmatrix.sync.aligned.m8n8.x4.shared.b16 {%0,%1,%2,%3}, [%4];"
                 : "=r"(r[0]), "=r"(r[1]), "=r"(r[2]), "=r"(r[3]) : "r"(a));
}
__device__ __forceinline__ void mmaT(float d[4], const uint32_t a[4],
                                     uint32_t b0, uint32_t b1) {
    asm volatile("mma.sync.aligned.m16n8k8.row.col.f32.tf32.tf32.f32 "
                 "{%0,%1,%2,%3},{%4,%5,%6,%7},{%8,%9},{%0,%1,%2,%3};"
                 : "+f"(d[0]), "+f"(d[1]), "+f"(d[2]), "+f"(d[3])
                 : "r"(a[0]), "r"(a[1]), "r"(a[2]), "r"(a[3]),
                   "r"(b0), "r"(b1));
}

// tf32-round a float array (float4-vectorized, grid-strided)
__device__ __forceinline__ void conv_arr(float* dst, const float* src, int n4,
                                         int gtid, int gstr) {
    for (int i = gtid; i < n4; i += gstr) {
        float4 v = ((const float4*)src)[i];
        v.x = tf32r(v.x); v.y = tf32r(v.y); v.z = tf32r(v.z); v.w = tf32r(v.w);
        ((float4*)dst)[i] = v;
    }
}

// One LSTM step for this CTA's (MB x NH) tile.
// All operands pre-rounded to tf32 -> pure cp.async staging, no cvt.
__device__ __forceinline__ void lstm_step(
    char* dsm,
    const float* __restrict__ hcur, float* __restrict__ hnext, float* __restrict__ cbuf,
    const float* __restrict__ Whh, const float* __restrict__ Wih,
    const float* __restrict__ bih, const float* __restrict__ bhh,
    const float* __restrict__ xptr, int xstride,
    int m0, int n0)
{
    const int tid = threadIdx.x;
    const int lane = tid & 31, warp = tid >> 5;
    const int wm = (warp & 1) * 32;      // warp m offset within CTA tile
    const int wn = (warp >> 1) * 32;     // warp gate-col offset

    // Loader mapping: 8 lanes cover one 128B row segment (conflict-free smem,
    // single global line per 8-lane phase).
    const int ar = tid >> 3;             // 0..31
    const int ac = (tid & 7) * 4;        // float offset within 32-float chunk row

    // A rows: ar and ar+32 (batch rows). B rows: ar + 32*j -> gate j, hid n0+ar.
    const float* ha0 = hcur + (size_t)(m0 + ar) * HH;
    const float* ha1 = hcur + (size_t)(m0 + ar + 32) * HH;
    const float* xa0 = xptr + (size_t)(m0 + ar) * xstride;
    const float* xa1 = xptr + (size_t)(m0 + ar + 32) * xstride;
    const float* whr[4];
    const float* wir[4];
#pragma unroll
    for (int j = 0; j < 4; j++) {
        whr[j] = Whh + (size_t)(j * HH + n0 + ar) * HH;
        wir[j] = Wih + (size_t)(j * HH + n0 + ar) * FF;
    }

    const uint32_t base = (uint32_t)__cvta_generic_to_shared(dsm);
    const uint32_t sA0 = base + (uint32_t)((ar * AST + ac) << 2);
    const uint32_t sA1 = base + (uint32_t)(((ar + 32) * AST + ac) << 2);
    const uint32_t sB  = base + (uint32_t)((MB * AST) << 2);

    auto issue = [&](int ci) {
        const uint32_t so = (uint32_t)((ci & (NSTG - 1)) * STG_BYTES);
        const int k0 = ci * KC;
        if (k0 < HH) {
            cpa16(sA0 + so, ha0 + k0 + ac);
            cpa16(sA1 + so, ha1 + k0 + ac);
#pragma unroll
            for (int j = 0; j < 4; j++)
                cpa16(sB + so + (uint32_t)(((ar + 32 * j) * BST + ac) << 2),
                      whr[j] + k0 + ac);
        } else {
            const int kk = k0 - HH;
            cpa16(sA0 + so, xa0 + kk + ac);
            cpa16(sA1 + so, xa1 + kk + ac);
#pragma unroll
            for (int j = 0; j < 4; j++)
                cpa16(sB + so + (uint32_t)(((ar + 32 * j) * BST + ac) << 2),
                      wir[j] + kk + ac);
        }
        asm volatile("cp.async.commit_group;" ::: "memory");
    };

    // ldmatrix per-lane addresses (x4 = m16 x k8; tiles: +8 rows / +4 k)
    const int lr = lane & 7, lt = lane >> 3;
    const int madd = (lt & 1) * 8;
    const int kadd = (lt >> 1) * 4;
    const uint32_t aA0 = base + (uint32_t)(((wm + lr + madd) * AST + kadd) << 2);
    const uint32_t aA1 = aA0 + (uint32_t)((16 * AST) << 2);
    const uint32_t aB0 = base + (uint32_t)((MB * AST) << 2)
                       + (uint32_t)(((wn + lr + madd) * BST + kadd) << 2);
    const uint32_t aB1 = aB0 + (uint32_t)((16 * BST) << 2);

    float acc[2][4][4];
#pragma unroll
    for (int mi = 0; mi < 2; mi++)
#pragma unroll
        for (int ni = 0; ni < 4; ni++)
#pragma unroll
            for (int q = 0; q < 4; q++) acc[mi][ni][q] = 0.0f;

    // prologue: 3 chunks in flight
    issue(0); issue(1); issue(2);

#pragma unroll 1
    for (int i = 0; i < NCHUNK; i++) {
        if (i + 3 >= NCHUNK)   // keep group count advancing at the tail
            asm volatile("cp.async.commit_group;" ::: "memory");
        asm volatile("cp.async.wait_group 2;" ::: "memory");
        __syncthreads();       // chunk i visible to all; iter i-1 readers done
        if (i + 3 < NCHUNK) issue(i + 3);

        const uint32_t so = (uint32_t)((i & (NSTG - 1)) * STG_BYTES);
#pragma unroll
        for (int kb = 0; kb < 4; kb++) {
            uint32_t A0[4], A1[4], B0[4], B1[4];
            ldsm4(A0, aA0 + so + kb * 32);
            ldsm4(A1, aA1 + so + kb * 32);
            ldsm4(B0, aB0 + so + kb * 32);
            ldsm4(B1, aB1 + so + kb * 32);
            mmaT(acc[0][0], A0, B0[0], B0[2]);
            mmaT(acc[0][1], A0, B0[1], B0[3]);
            mmaT(acc[0][2], A0, B1[0], B1[2]);
            mmaT(acc[0][3], A0, B1[1], B1[3]);
            mmaT(acc[1][0], A1, B0[0], B0[2]);
            mmaT(acc[1][1], A1, B0[1], B0[3]);
            mmaT(acc[1][2], A1, B1[0], B1[2]);
            mmaT(acc[1][3], A1, B1[1], B1[3]);
        }
    }

    // epilogue: spill accumulators to Gs (row-major [batch][gatecol])
    float (*Gs)[GST] = (float (*)[GST])dsm;
    __syncthreads();
#pragma unroll
    for (int mi = 0; mi < 2; mi++)
#pragma unroll
        for (int ni = 0; ni < 4; ni++) {
            int r = wm + mi * 16 + (lane >> 2);
            int c = wn + ni * 8 + (lane & 3) * 2;
            *(float2*)&Gs[r][c]     = make_float2(acc[mi][ni][0], acc[mi][ni][1]);
            *(float2*)&Gs[r + 8][c] = make_float2(acc[mi][ni][2], acc[mi][ni][3]);
        }
    __syncthreads();

    // pointwise LSTM update; h stored tf32-rounded (what the next mma consumes)
    const int hid = tid & 31;
    const int rb = tid >> 5;
    const float bi = bih[0 * HH + n0 + hid] + bhh[0 * HH + n0 + hid];
    const float bf = bih[1 * HH + n0 + hid] + bhh[1 * HH + n0 + hid];
    const float bg = bih[2 * HH + n0 + hid] + bhh[2 * HH + n0 + hid];
    const float bo = bih[3 * HH + n0 + hid] + bhh[3 * HH + n0 + hid];
#pragma unroll
    for (int it = 0; it < (MB * NH) / NTHR; it++) {
        int r = rb + it * 8;
        float iv = Gs[r][hid]      + bi;
        float fv = Gs[r][32 + hid] + bf;
        float gv = Gs[r][64 + hid] + bg;
        float ov = Gs[r][96 + hid] + bo;
        int gi = (m0 + r) * HH + n0 + hid;
        float cold = cbuf[gi];
        float cn = sigm(fv) * cold + sigm(iv) * tanh_f(gv);
        float hn = sigm(ov) * tanh_f(cn);
        cbuf[gi] = cn;
        hnext[gi] = tf32r(hn);
    }
}

// pred = h @ W_fc^T + b_fc ; write to out[b, t, :] and g_x (tf32-rounded feed).
__device__ __forceinline__ void pred_step(
    char* dsm, const float* __restrict__ h,
    const float* __restrict__ Wfc, const float* __restrict__ bfc,
    float* __restrict__ out, int t, int T)
{
    float (*Hs)[HH] = (float (*)[HH])dsm;
    const int tid = threadIdx.x;
    const int pr0 = blockIdx.x * 2;

#pragma unroll
    for (int q = 0; q < 2; q++) {
        int f4 = tid + q * 256;
        int r = f4 >> 8;
        int c4 = f4 & 255;
        *(float4*)&Hs[r][c4 * 4] = ldg4(&h[(size_t)(pr0 + r) * HH + c4 * 4]);
    }
    __syncthreads();

    const int warp = tid >> 5, lane = tid & 31;
    for (int oi = warp; oi < 128; oi += 8) {
        int r = oi >> 6;
        int f = oi & 63;
        const float4* wrow = (const float4*)&Wfc[(size_t)f * HH];
        const float4* hrow = (const float4*)&Hs[r][0];
        float s = 0.0f;
#pragma unroll 4
        for (int k4 = lane; k4 < 256; k4 += 32) {
            float4 w = wrow[k4];
            float4 hv = hrow[k4];
            s += w.x * hv.x + w.y * hv.y + w.z * hv.z + w.w * hv.w;
        }
#pragma unroll
        for (int off = 16; off; off >>= 1)
            s += __shfl_xor_sync(0xffffffffu, s, off);
        if (lane == 0) {
            float p = s + bfc[f];
            int b = pr0 + r;
            out[(size_t)b * T * FF + t * FF + f] = p;
            g_x[b * FF + f] = tf32r(p);
        }
    }
    __syncthreads();
}

__global__ void __launch_bounds__(NTHR) s2s_kernel(
    const float* __restrict__ x_seq,
    const float* __restrict__ Wih_e, const float* __restrict__ Whh_e,
    const float* __restrict__ bih_e, const float* __restrict__ bhh_e,
    const float* __restrict__ Wih_d, const float* __restrict__ Whh_d,
    const float* __restrict__ bih_d, const float* __restrict__ bhh_d,
    const float* __restrict__ Wfc, const float* __restrict__ bfc,
    const int* __restrict__ plen,
    float* __restrict__ out)
{
    extern __shared__ char dsm[];
    const int tid = threadIdx.x;
    const int m0 = (blockIdx.x >> 5) * MB;
    const int n0 = (blockIdx.x & 31) * NH;

    // Phase 0: tf32-preconvert weights + inputs; zero h0/c0 (grid-strided)
    {
        const int gtid = blockIdx.x * NTHR + tid;
        const int gstr = NCTA * NTHR;
        conv_arr(g_whh_e, Whh_e, 4 * HH * HH / 4, gtid, gstr);
        conv_arr(g_wih_e, Wih_e, 4 * HH * FF / 4, gtid, gstr);
        conv_arr(g_whh_d, Whh_d, 4 * HH * HH / 4, gtid, gstr);
        conv_arr(g_wih_d, Wih_d, 4 * HH * FF / 4, gtid, gstr);
        conv_arr(g_xs, x_seq, BB * SS * FF / 4, gtid, gstr);
        float4 z = make_float4(0.f, 0.f, 0.f, 0.f);
        for (int i = gtid; i < BB * HH / 4; i += gstr) {
            ((float4*)g_h[0])[i] = z;
            ((float4*)g_c)[i] = z;
        }
    }
    grid_barrier();

    int cur = 0;
    // ---- encoder: 512 steps ----
    for (int t = 0; t < SS; t++) {
        lstm_step(dsm, g_h[cur], g_h[cur ^ 1], g_c,
                  g_whh_e, g_wih_e, bih_e, bhh_e,
                  g_xs + (size_t)t * FF, SS * FF, m0, n0);
        grid_barrier();
        cur ^= 1;
    }

    // ---- decoder ----
    const int T = *plen;
    for (int t = 0; t < T; t++) {
        const float* xp = (t == 0) ? (g_xs + (size_t)(SS - 1) * FF) : g_x;
        const int xs = (t == 0) ? (SS * FF) : FF;
        lstm_step(dsm, g_h[cur], g_h[cur ^ 1], g_c,
                  g_whh_d, g_wih_d, bih_d, bhh_d, xp, xs, m0, n0);
        grid_barrier();
        cur ^= 1;
        pred_step(dsm, g_h[cur], Wfc, bfc, out, t, T);
        grid_barrier();
    }
}

extern "C" void kernel_launch(void* const* d_in, const int* in_sizes, int n_in,
                              void* d_out, int out_size)
{
    const float* x_seq = (const float*)d_in[0];
    const float* Wih_e = (const float*)d_in[1];
    const float* Whh_e = (const float*)d_in[2];
    const float* bih_e = (const float*)d_in[3];
    const float* bhh_e = (const float*)d_in[4];
    const float* Wih_d = (const float*)d_in[5];
    const float* Whh_d = (const float*)d_in[6];
    const float* bih_d = (const float*)d_in[7];
    const float* bhh_d = (const float*)d_in[8];
    const float* Wfc   = (const float*)d_in[9];
    const float* bfc   = (const float*)d_in[10];
    const int*   plen  = (const int*)d_in[11];
    float* out = (float*)d_out;

    cudaFuncSetAttribute(s2s_kernel,
                         cudaFuncAttributeMaxDynamicSharedMemorySize, SMEM_BYTES);
    s2s_kernel<<<NCTA, NTHR, SMEM_BYTES>>>(x_seq, Wih_e, Whh_e, bih_e, bhh_e,
                                           Wih_d, Whh_d, bih_d, bhh_d,
                                           Wfc, bfc, plen, out);
}

// round 5
// speedup vs baseline: 5.9970x; 1.6706x over previous
#include <cuda_runtime.h>
#include <cuda_fp16.h>
#include <cstdint>

// Shapes (fixed)
#define BB 256
#define SS 512
#define FF 64
#define HH 1024

#define NCTA 128    // 2 batch-blocks x 64 hidden-blocks
#define NTHR 256
#define MB 128      // batch rows per CTA
#define NH 16       // hidden cols per CTA
#define GT 64       // gate rows per CTA = 4*NH
#define KC 64       // K chunk (four k16 mma sub-steps)
#define KTOT (HH + FF)          // 1088
#define NCHUNK (KTOT / KC)      // 17
#define NSTG 4

#define WST 1096    // weight smem row stride (halves); 548 words, 548%32=4 -> ldsm ok
#define AST 72      // A smem row stride (halves); 36 words, 36%32=4 -> ldsm ok
#define GST 68

#define WBYTES (GT * WST * 2)           // 140288
#define ASTG_BYTES (MB * AST * 2)       // 18432
#define SMEM_BYTES (WBYTES + NSTG * ASTG_BYTES)   // 214016

// Persistent state (no allocations allowed)
__device__ __half g_h[2][BB * HH];
__device__ float  g_c[BB * HH];
__device__ __half g_x[BB * FF];
__device__ __half g_xs[BB * SS * FF];
__device__ unsigned g_bar_cnt;
__device__ unsigned g_bar_gen;

__device__ __forceinline__ void grid_barrier() {
    __syncthreads();
    if (threadIdx.x == 0) {
        __threadfence();
        unsigned gen = *(volatile unsigned*)&g_bar_gen;
        if (atomicAdd(&g_bar_cnt, 1u) == NCTA - 1u) {
            atomicExch(&g_bar_cnt, 0u);
            __threadfence();
            atomicAdd(&g_bar_gen, 1u);
        } else {
            while (*(volatile unsigned*)&g_bar_gen == gen) { }
        }
        __threadfence();
    }
    __syncthreads();
}

__device__ __forceinline__ float sigm(float x) {
    return 1.0f / (1.0f + __expf(-x));
}
__device__ __forceinline__ float tanh_f(float x) {
    float xx = fminf(fmaxf(x, -15.0f), 15.0f);
    float e = __expf(2.0f * xx);
    return (e - 1.0f) / (e + 1.0f);
}
__device__ __forceinline__ void cpa16(uint32_t s, const void* g) {
    asm volatile("cp.async.cg.shared.global [%0], [%1], 16;" :: "r"(s), "l"(g));
}
__device__ __forceinline__ void ldsm4(uint32_t r[4], uint32_t a) {
    asm volatile("ldmatrix.sync.aligned.m8n8.x4.shared.b16 {%0,%1,%2,%3}, [%4];"
                 : "=r"(r[0]), "=r"(r[1]), "=r"(r[2]), "=r"(r[3]) : "r"(a));
}
__device__ __forceinline__ void mmaH(float d[4], const uint32_t a[4],
                                     uint32_t b0, uint32_t b1) {
    asm volatile("mma.sync.aligned.m16n8k16.row.col.f32.f16.f16.f32 "
                 "{%0,%1,%2,%3},{%4,%5,%6,%7},{%8,%9},{%0,%1,%2,%3};"
                 : "+f"(d[0]), "+f"(d[1]), "+f"(d[2]), "+f"(d[3])
                 : "r"(a[0]), "r"(a[1]), "r"(a[2]), "r"(a[3]),
                   "r"(b0), "r"(b1));
}

// Load this CTA's gate-row weight slice (fp16) into resident smem.
// Row c (0..63): gate g=c>>4, hid=n0+(c&15); k<1024 from Whh, else Wih.
__device__ void load_weights(__half* W, const float* __restrict__ Whh,
                             const float* __restrict__ Wih, int n0) {
    const int tid = threadIdx.x;
    for (int idx = tid; idx < GT * KTOT; idx += NTHR) {
        int row = idx / KTOT;
        int k = idx - row * KTOT;
        int g = row >> 4, hid = n0 + (row & 15);
        float v = (k < HH) ? Whh[(size_t)(g * HH + hid) * HH + k]
                           : Wih[(size_t)(g * HH + hid) * FF + (k - HH)];
        W[row * WST + k] = __float2half_rn(v);
    }
}

// One LSTM step for this CTA's (MB x NH) tile. Weights resident in smem.
__device__ __forceinline__ void lstm_step(
    char* dsm,
    const __half* __restrict__ hcur, __half* __restrict__ hnext,
    float* __restrict__ cbuf,
    const float* __restrict__ bih, const float* __restrict__ bhh,
    const __half* __restrict__ xptr, int xstride,
    int m0, int n0)
{
    const int tid = threadIdx.x;
    const int lane = tid & 31, warp = tid >> 5;
    const int wm = (warp >> 1) * 32;     // warp m offset (4 warps in M)
    const int wn = (warp & 1) * 32;      // warp gate-col offset (2 warps in N)

    const uint32_t base = (uint32_t)__cvta_generic_to_shared(dsm);
    const uint32_t Wbase = base;
    const uint32_t Abase = base + (uint32_t)WBYTES;

    // ---- A loader: 128 rows x 8 segs of 16B per chunk; 4 cp.async/thread ----
    int lrow[4], lseg[4];
    const __half* hrow[4];
    const __half* xrow[4];
#pragma unroll
    for (int q = 0; q < 4; q++) {
        int idx = tid + q * 256;
        lrow[q] = idx >> 3;
        lseg[q] = idx & 7;
        hrow[q] = hcur + (size_t)(m0 + lrow[q]) * HH + lseg[q] * 8;
        xrow[q] = xptr + (size_t)(m0 + lrow[q]) * xstride + lseg[q] * 8;
    }
    auto issue = [&](int ci) {
        const uint32_t so = (uint32_t)((ci & (NSTG - 1)) * ASTG_BYTES);
        const int k0 = ci * KC;
#pragma unroll
        for (int q = 0; q < 4; q++) {
            uint32_t dst = Abase + so + (uint32_t)(lrow[q] * (AST * 2) + lseg[q] * 16);
            if (k0 < HH) cpa16(dst, hrow[q] + k0);
            else         cpa16(dst, xrow[q] + (k0 - HH));
        }
        asm volatile("cp.async.commit_group;" ::: "memory");
    };

    // ---- ldmatrix lane addressing ----
    const int lr = lane & 7, lt = lane >> 3;
    const int madd = (lt & 1) * 8;       // tiles 1,3: +8 rows
    const int kq = (lt >> 1) * 8;        // tiles 2,3: +8 halves (=16B) in k
    const uint32_t aA0 = Abase + (uint32_t)(((wm + lr + madd) * AST + kq) * 2);
    const uint32_t aA1 = aA0 + (uint32_t)(16 * AST * 2);
    const uint32_t bB0 = Wbase + (uint32_t)(((wn + lr + madd) * WST + kq) * 2);
    const uint32_t bB1 = bB0 + (uint32_t)(16 * WST * 2);

    float acc[2][4][4];
#pragma unroll
    for (int mi = 0; mi < 2; mi++)
#pragma unroll
        for (int ni = 0; ni < 4; ni++)
#pragma unroll
            for (int q = 0; q < 4; q++) acc[mi][ni][q] = 0.0f;

    issue(0); issue(1); issue(2);

#pragma unroll 1
    for (int i = 0; i < NCHUNK; i++) {
        if (i + 3 >= NCHUNK)
            asm volatile("cp.async.commit_group;" ::: "memory");
        asm volatile("cp.async.wait_group 2;" ::: "memory");
        __syncthreads();
        if (i + 3 < NCHUNK) issue(i + 3);

        const uint32_t so = (uint32_t)((i & (NSTG - 1)) * ASTG_BYTES);
        const uint32_t ko = (uint32_t)(i * KC * 2);   // weight k offset (bytes)
#pragma unroll
        for (int kb = 0; kb < 4; kb++) {
            uint32_t A0[4], A1[4], B0[4], B1[4];
            ldsm4(A0, aA0 + so + kb * 32);
            ldsm4(A1, aA1 + so + kb * 32);
            ldsm4(B0, bB0 + ko + kb * 32);
            ldsm4(B1, bB1 + ko + kb * 32);
            mmaH(acc[0][0], A0, B0[0], B0[2]);
            mmaH(acc[0][1], A0, B0[1], B0[3]);
            mmaH(acc[0][2], A0, B1[0], B1[2]);
            mmaH(acc[0][3], A0, B1[1], B1[3]);
            mmaH(acc[1][0], A1, B0[0], B0[2]);
            mmaH(acc[1][1], A1, B0[1], B0[3]);
            mmaH(acc[1][2], A1, B1[0], B1[2]);
            mmaH(acc[1][3], A1, B1[1], B1[3]);
        }
    }

    // epilogue: gates to smem (overlay A staging region)
    asm volatile("cp.async.wait_group 0;" ::: "memory");
    __syncthreads();
    float (*Gs)[GST] = (float (*)[GST])(dsm + WBYTES);
#pragma unroll
    for (int mi = 0; mi < 2; mi++)
#pragma unroll
        for (int ni = 0; ni < 4; ni++) {
            int r = wm + mi * 16 + (lane >> 2);
            int c = wn + ni * 8 + (lane & 3) * 2;
            *(float2*)&Gs[r][c]     = make_float2(acc[mi][ni][0], acc[mi][ni][1]);
            *(float2*)&Gs[r + 8][c] = make_float2(acc[mi][ni][2], acc[mi][ni][3]);
        }
    __syncthreads();

    // pointwise LSTM update (2048 elems, 8 per thread)
    const int hid = tid & 15;
    const int rb = tid >> 4;
    const float bi = bih[0 * HH + n0 + hid] + bhh[0 * HH + n0 + hid];
    const float bf = bih[1 * HH + n0 + hid] + bhh[1 * HH + n0 + hid];
    const float bg = bih[2 * HH + n0 + hid] + bhh[2 * HH + n0 + hid];
    const float bo = bih[3 * HH + n0 + hid] + bhh[3 * HH + n0 + hid];
#pragma unroll
    for (int it = 0; it < (MB * NH) / NTHR; it++) {
        int r = rb + it * 16;
        float iv = Gs[r][hid]      + bi;
        float fv = Gs[r][16 + hid] + bf;
        float gv = Gs[r][32 + hid] + bg;
        float ov = Gs[r][48 + hid] + bo;
        int gi = (m0 + r) * HH + n0 + hid;
        float cold = cbuf[gi];
        float cn = sigm(fv) * cold + sigm(iv) * tanh_f(gv);
        float hn = sigm(ov) * tanh_f(cn);
        cbuf[gi] = cn;
        hnext[gi] = __float2half_rn(hn);
    }
}

// pred = h @ W_fc^T + b_fc ; out[b,t,:] fp32, g_x fp16 feed.
__device__ __forceinline__ void pred_step(
    char* dsm, const __half* __restrict__ h,
    const float* __restrict__ Wfc, const float* __restrict__ bfc,
    float* __restrict__ out, int t, int T)
{
    float (*Hs)[HH] = (float (*)[HH])(dsm + WBYTES);
    const int tid = threadIdx.x;
    const int pr0 = blockIdx.x * 2;

    // stage 2 h rows (half -> float): 1024 half2, 4 per thread
#pragma unroll
    for (int q = 0; q < 4; q++) {
        int idx = tid + q * 256;
        int r = idx >> 9;
        int c2 = idx & 511;
        float2 f = __half22float2(((const __half2*)(h + (size_t)(pr0 + r) * HH))[c2]);
        Hs[r][c2 * 2]     = f.x;
        Hs[r][c2 * 2 + 1] = f.y;
    }
    __syncthreads();

    const int warp = tid >> 5, lane = tid & 31;
    for (int oi = warp; oi < 128; oi += 8) {
        int r = oi >> 6;
        int f = oi & 63;
        const float4* wrow = (const float4*)&Wfc[(size_t)f * HH];
        const float4* hrow = (const float4*)&Hs[r][0];
        float s = 0.0f;
#pragma unroll 4
        for (int k4 = lane; k4 < 256; k4 += 32) {
            float4 w = wrow[k4];
            float4 hv = hrow[k4];
            s += w.x * hv.x + w.y * hv.y + w.z * hv.z + w.w * hv.w;
        }
#pragma unroll
        for (int off = 16; off; off >>= 1)
            s += __shfl_xor_sync(0xffffffffu, s, off);
        if (lane == 0) {
            float p = s + bfc[f];
            int b = pr0 + r;
            out[(size_t)b * T * FF + t * FF + f] = p;
            g_x[b * FF + f] = __float2half_rn(p);
        }
    }
    __syncthreads();
}

__global__ void __launch_bounds__(NTHR) s2s_kernel(
    const float* __restrict__ x_seq,
    const float* __restrict__ Wih_e, const float* __restrict__ Whh_e,
    const float* __restrict__ bih_e, const float* __restrict__ bhh_e,
    const float* __restrict__ Wih_d, const float* __restrict__ Whh_d,
    const float* __restrict__ bih_d, const float* __restrict__ bhh_d,
    const float* __restrict__ Wfc, const float* __restrict__ bfc,
    const int* __restrict__ plen,
    float* __restrict__ out)
{
    extern __shared__ char dsm[];
    const int tid = threadIdx.x;
    const int m0 = (blockIdx.x >> 6) * MB;        // 2 batch blocks
    const int n0 = (blockIdx.x & 63) * NH;        // 64 hidden blocks

    // Phase 0: resident encoder weights (per-CTA) + global x->fp16, h/c zero
    load_weights((__half*)dsm, Whh_e, Wih_e, n0);
    {
        const int gtid = blockIdx.x * NTHR + tid;
        const int gstr = NCTA * NTHR;
        for (int i = gtid; i < BB * SS * FF / 4; i += gstr) {
            float4 v = ((const float4*)x_seq)[i];
            ((__half2*)g_xs)[i * 2]     = __floats2half2_rn(v.x, v.y);
            ((__half2*)g_xs)[i * 2 + 1] = __floats2half2_rn(v.z, v.w);
        }
        uint4 z4 = make_uint4(0, 0, 0, 0);
        for (int i = gtid; i < BB * HH / 8; i += gstr)
            ((uint4*)g_h[0])[i] = z4;
        float4 zf = make_float4(0.f, 0.f, 0.f, 0.f);
        for (int i = gtid; i < BB * HH / 4; i += gstr)
            ((float4*)g_c)[i] = zf;
    }
    grid_barrier();

    int cur = 0;
    // ---- encoder ----
    for (int t = 0; t < SS; t++) {
        lstm_step(dsm, g_h[cur], g_h[cur ^ 1], g_c, bih_e, bhh_e,
                  g_xs + (size_t)t * FF, SS * FF, m0, n0);
        grid_barrier();
        cur ^= 1;
    }

    // swap to decoder weights (per-CTA smem, only local sync needed)
    __syncthreads();
    load_weights((__half*)dsm, Whh_d, Wih_d, n0);
    __syncthreads();

    // ---- decoder ----
    const int T = *plen;
    for (int t = 0; t < T; t++) {
        const __half* xp = (t == 0) ? (g_xs + (size_t)(SS - 1) * FF) : g_x;
        const int xs = (t == 0) ? (SS * FF) : FF;
        lstm_step(dsm, g_h[cur], g_h[cur ^ 1], g_c, bih_d, bhh_d,
                  xp, xs, m0, n0);
        grid_barrier();
        cur ^= 1;
        pred_step(dsm, g_h[cur], Wfc, bfc, out, t, T);
        grid_barrier();
    }
}

extern "C" void kernel_launch(void* const* d_in, const int* in_sizes, int n_in,
                              void* d_out, int out_size)
{
    const float* x_seq = (const float*)d_in[0];
    const float* Wih_e = (const float*)d_in[1];
    const float* Whh_e = (const float*)d_in[2];
    const float* bih_e = (const float*)d_in[3];
    const float* bhh_e = (const float*)d_in[4];
    const float* Wih_d = (const float*)d_in[5];
    const float* Whh_d = (const float*)d_in[6];
    const float* bih_d = (const float*)d_in[7];
    const float* bhh_d = (const float*)d_in[8];
    const float* Wfc   = (const float*)d_in[9];
    const float* bfc   = (const float*)d_in[10];
    const int*   plen  = (const int*)d_in[11];
    float* out = (float*)d_out;

    cudaFuncSetAttribute(s2s_kernel,
                         cudaFuncAttributeMaxDynamicSharedMemorySize, SMEM_BYTES);
    s2s_kernel<<<NCTA, NTHR, SMEM_BYTES>>>(x_seq, Wih_e, Whh_e, bih_e, bhh_e,
                                           Wih_d, Whh_d, bih_d, bhh_d,
                                           Wfc, bfc, plen, out);
}

// round 6
// speedup vs baseline: 6.4526x; 1.0760x over previous
#include <cuda_runtime.h>
#include <cuda_fp16.h>
#include <cstdint>

// Shapes (fixed)
#define BB 256
#define SS 512
#define FF 64
#define HH 1024

#define NCTA 128    // 2 batch-blocks x 64 hidden-blocks
#define NTHR 512    // 16 warps: 4m x 2n x 2k-split
#define MB 128      // batch rows per CTA
#define NH 16       // hidden cols per CTA
#define GT 64       // gate rows per CTA = 4*NH
#define KC 64       // K chunk (four k16 mma sub-steps; 2 per k-warp)
#define KTOT (HH + FF)          // 1088
#define NCHUNK (KTOT / KC)      // 17
#define NSTG 4

#define WST 1096    // weight smem row stride (halves); conflict-free ldsm
#define AST 72      // A smem row stride (halves); conflict-free ldsm
#define GST 68

#define WBYTES (GT * WST * 2)           // 140288
#define ASTG_BYTES (MB * AST * 2)       // 18432
#define SMEM_BYTES (WBYTES + NSTG * ASTG_BYTES)   // 214016

// Persistent state (no allocations allowed)
__device__ __half g_h[2][BB * HH];
__device__ float  g_c[BB * HH];
__device__ __half g_x[BB * FF];
__device__ __half g_xs[BB * SS * FF];
__device__ unsigned g_bar_cnt;
__device__ unsigned g_bar_gen;

__device__ __forceinline__ void grid_barrier() {
    __syncthreads();
    if (threadIdx.x == 0) {
        __threadfence();
        unsigned gen = *(volatile unsigned*)&g_bar_gen;
        if (atomicAdd(&g_bar_cnt, 1u) == NCTA - 1u) {
            atomicExch(&g_bar_cnt, 0u);
            __threadfence();
            atomicAdd(&g_bar_gen, 1u);
        } else {
            while (*(volatile unsigned*)&g_bar_gen == gen) { }
        }
        __threadfence();
    }
    __syncthreads();
}

__device__ __forceinline__ float sigm(float x) {
    return 1.0f / (1.0f + __expf(-x));
}
__device__ __forceinline__ float tanh_f(float x) {
    float xx = fminf(fmaxf(x, -15.0f), 15.0f);
    float e = __expf(2.0f * xx);
    return (e - 1.0f) / (e + 1.0f);
}
__device__ __forceinline__ void cpa16(uint32_t s, const void* g) {
    asm volatile("cp.async.cg.shared.global [%0], [%1], 16;" :: "r"(s), "l"(g));
}
__device__ __forceinline__ void ldsm4(uint32_t r[4], uint32_t a) {
    asm volatile("ldmatrix.sync.aligned.m8n8.x4.shared.b16 {%0,%1,%2,%3}, [%4];"
                 : "=r"(r[0]), "=r"(r[1]), "=r"(r[2]), "=r"(r[3]) : "r"(a));
}
__device__ __forceinline__ void mmaH(float d[4], const uint32_t a[4],
                                     uint32_t b0, uint32_t b1) {
    asm volatile("mma.sync.aligned.m16n8k16.row.col.f32.f16.f16.f32 "
                 "{%0,%1,%2,%3},{%4,%5,%6,%7},{%8,%9},{%0,%1,%2,%3};"
                 : "+f"(d[0]), "+f"(d[1]), "+f"(d[2]), "+f"(d[3])
                 : "r"(a[0]), "r"(a[1]), "r"(a[2]), "r"(a[3]),
                   "r"(b0), "r"(b1));
}

// Load this CTA's gate-row weight slice (fp16) into resident smem.
__device__ void load_weights(__half* W, const float* __restrict__ Whh,
                             const float* __restrict__ Wih, int n0) {
    const int tid = threadIdx.x;
    for (int idx = tid; idx < GT * KTOT; idx += NTHR) {
        int row = idx / KTOT;
        int k = idx - row * KTOT;
        int g = row >> 4, hid = n0 + (row & 15);
        float v = (k < HH) ? Whh[(size_t)(g * HH + hid) * HH + k]
                           : Wih[(size_t)(g * HH + hid) * FF + (k - HH)];
        W[row * WST + k] = __float2half_rn(v);
    }
}

// One LSTM step for this CTA's (MB x NH) tile. Weights resident in smem.
// 16 warps: kw = warp>>3 splits the 4 k16 sub-steps of each chunk (2 each).
__device__ __forceinline__ void lstm_step(
    char* dsm,
    const __half* __restrict__ hcur, __half* __restrict__ hnext,
    float* __restrict__ cbuf,
    const float* __restrict__ bih, const float* __restrict__ bhh,
    const __half* __restrict__ xptr, int xstride,
    int m0, int n0)
{
    const int tid = threadIdx.x;
    const int lane = tid & 31, warp = tid >> 5;
    const int kw = warp >> 3;                 // 0/1: k-split half
    const int wm = ((warp >> 1) & 3) * 32;    // 4 m groups
    const int wn = (warp & 1) * 32;           // 2 gate-col groups

    const uint32_t base = (uint32_t)__cvta_generic_to_shared(dsm);
    const uint32_t Wbase = base;
    const uint32_t Abase = base + (uint32_t)WBYTES;

    // ---- A loader: 128 rows x 8 segs of 16B per chunk; 2 cp.async/thread ----
    int lrow[2], lseg[2];
    const __half* hrow[2];
    const __half* xrow[2];
#pragma unroll
    for (int q = 0; q < 2; q++) {
        int idx = tid + q * NTHR;
        lrow[q] = idx >> 3;
        lseg[q] = idx & 7;
        hrow[q] = hcur + (size_t)(m0 + lrow[q]) * HH + lseg[q] * 8;
        xrow[q] = xptr + (size_t)(m0 + lrow[q]) * xstride + lseg[q] * 8;
    }
    auto issue = [&](int ci) {
        const uint32_t so = (uint32_t)((ci & (NSTG - 1)) * ASTG_BYTES);
        const int k0 = ci * KC;
#pragma unroll
        for (int q = 0; q < 2; q++) {
            uint32_t dst = Abase + so + (uint32_t)(lrow[q] * (AST * 2) + lseg[q] * 16);
            if (k0 < HH) cpa16(dst, hrow[q] + k0);
            else         cpa16(dst, xrow[q] + (k0 - HH));
        }
        asm volatile("cp.async.commit_group;" ::: "memory");
    };

    // ---- ldmatrix lane addressing ----
    const int lr = lane & 7, lt = lane >> 3;
    const int madd = (lt & 1) * 8;       // tiles 1,3: +8 rows
    const int kq = (lt >> 1) * 8;        // tiles 2,3: +8 halves in k
    const uint32_t aA0 = Abase + (uint32_t)(((wm + lr + madd) * AST + kq) * 2);
    const uint32_t aA1 = aA0 + (uint32_t)(16 * AST * 2);
    const uint32_t bB0 = Wbase + (uint32_t)(((wn + lr + madd) * WST + kq) * 2);
    const uint32_t bB1 = bB0 + (uint32_t)(16 * WST * 2);

    float acc[2][4][4];
#pragma unroll
    for (int mi = 0; mi < 2; mi++)
#pragma unroll
        for (int ni = 0; ni < 4; ni++)
#pragma unroll
            for (int q = 0; q < 4; q++) acc[mi][ni][q] = 0.0f;

    issue(0); issue(1); issue(2);

#pragma unroll 1
    for (int i = 0; i < NCHUNK; i++) {
        if (i + 3 >= NCHUNK)
            asm volatile("cp.async.commit_group;" ::: "memory");
        asm volatile("cp.async.wait_group 2;" ::: "memory");
        __syncthreads();
        if (i + 3 < NCHUNK) issue(i + 3);

        const uint32_t so = (uint32_t)((i & (NSTG - 1)) * ASTG_BYTES);
        const uint32_t ko = (uint32_t)(i * KC * 2);   // weight k offset (bytes)
        // this k-warp's two k16 sub-steps: kb = kw*2 + {0,1}
#pragma unroll
        for (int kb2 = 0; kb2 < 2; kb2++) {
            const int kb = kw * 2 + kb2;
            uint32_t A0[4], A1[4], B0[4], B1[4];
            ldsm4(A0, aA0 + so + kb * 32);
            ldsm4(A1, aA1 + so + kb * 32);
            ldsm4(B0, bB0 + ko + kb * 32);
            ldsm4(B1, bB1 + ko + kb * 32);
            mmaH(acc[0][0], A0, B0[0], B0[2]);
            mmaH(acc[0][1], A0, B0[1], B0[3]);
            mmaH(acc[0][2], A0, B1[0], B1[2]);
            mmaH(acc[0][3], A0, B1[1], B1[3]);
            mmaH(acc[1][0], A1, B0[0], B0[2]);
            mmaH(acc[1][1], A1, B0[1], B0[3]);
            mmaH(acc[1][2], A1, B1[0], B1[2]);
            mmaH(acc[1][3], A1, B1[1], B1[3]);
        }
    }

    // epilogue: k-split merge in Gs (overlay A staging region)
    asm volatile("cp.async.wait_group 0;" ::: "memory");
    __syncthreads();
    float (*Gs)[GST] = (float (*)[GST])(dsm + WBYTES);
    if (kw == 0) {
#pragma unroll
        for (int mi = 0; mi < 2; mi++)
#pragma unroll
            for (int ni = 0; ni < 4; ni++) {
                int r = wm + mi * 16 + (lane >> 2);
                int c = wn + ni * 8 + (lane & 3) * 2;
                *(float2*)&Gs[r][c]     = make_float2(acc[mi][ni][0], acc[mi][ni][1]);
                *(float2*)&Gs[r + 8][c] = make_float2(acc[mi][ni][2], acc[mi][ni][3]);
            }
    }
    __syncthreads();
    if (kw == 1) {
#pragma unroll
        for (int mi = 0; mi < 2; mi++)
#pragma unroll
            for (int ni = 0; ni < 4; ni++) {
                int r = wm + mi * 16 + (lane >> 2);
                int c = wn + ni * 8 + (lane & 3) * 2;
                float2 p0 = *(const float2*)&Gs[r][c];
                float2 p1 = *(const float2*)&Gs[r + 8][c];
                *(float2*)&Gs[r][c] =
                    make_float2(p0.x + acc[mi][ni][0], p0.y + acc[mi][ni][1]);
                *(float2*)&Gs[r + 8][c] =
                    make_float2(p1.x + acc[mi][ni][2], p1.y + acc[mi][ni][3]);
            }
    }
    __syncthreads();

    // pointwise LSTM update (2048 elems, 4 per thread)
    const int hid = tid & 15;
    const int rb = tid >> 4;      // 0..31
    const float bi = bih[0 * HH + n0 + hid] + bhh[0 * HH + n0 + hid];
    const float bf = bih[1 * HH + n0 + hid] + bhh[1 * HH + n0 + hid];
    const float bg = bih[2 * HH + n0 + hid] + bhh[2 * HH + n0 + hid];
    const float bo = bih[3 * HH + n0 + hid] + bhh[3 * HH + n0 + hid];
#pragma unroll
    for (int it = 0; it < (MB * NH) / NTHR; it++) {
        int r = rb + it * 32;
        float iv = Gs[r][hid]      + bi;
        float fv = Gs[r][16 + hid] + bf;
        float gv = Gs[r][32 + hid] + bg;
        float ov = Gs[r][48 + hid] + bo;
        int gi = (m0 + r) * HH + n0 + hid;
        float cold = cbuf[gi];
        float cn = sigm(fv) * cold + sigm(iv) * tanh_f(gv);
        float hn = sigm(ov) * tanh_f(cn);
        cbuf[gi] = cn;
        hnext[gi] = __float2half_rn(hn);
    }
}

// pred = h @ W_fc^T + b_fc ; out[b,t,:] fp32, g_x fp16 feed.
__device__ __forceinline__ void pred_step(
    char* dsm, const __half* __restrict__ h,
    const float* __restrict__ Wfc, const float* __restrict__ bfc,
    float* __restrict__ out, int t, int T)
{
    float (*Hs)[HH] = (float (*)[HH])(dsm + WBYTES);
    const int tid = threadIdx.x;
    const int pr0 = blockIdx.x * 2;

    // stage 2 h rows (half -> float): 1024 half2, 2 per thread
#pragma unroll
    for (int q = 0; q < 2; q++) {
        int idx = tid + q * NTHR;
        int r = idx >> 9;
        int c2 = idx & 511;
        float2 f = __half22float2(((const __half2*)(h + (size_t)(pr0 + r) * HH))[c2]);
        Hs[r][c2 * 2]     = f.x;
        Hs[r][c2 * 2 + 1] = f.y;
    }
    __syncthreads();

    const int warp = tid >> 5, lane = tid & 31;
    for (int oi = warp; oi < 128; oi += 16) {
        int r = oi >> 6;
        int f = oi & 63;
        const float4* wrow = (const float4*)&Wfc[(size_t)f * HH];
        const float4* hrow = (const float4*)&Hs[r][0];
        float s = 0.0f;
#pragma unroll 4
        for (int k4 = lane; k4 < 256; k4 += 32) {
            float4 w = wrow[k4];
            float4 hv = hrow[k4];
            s += w.x * hv.x + w.y * hv.y + w.z * hv.z + w.w * hv.w;
        }
#pragma unroll
        for (int off = 16; off; off >>= 1)
            s += __shfl_xor_sync(0xffffffffu, s, off);
        if (lane == 0) {
            float p = s + bfc[f];
            int b = pr0 + r;
            out[(size_t)b * T * FF + t * FF + f] = p;
            g_x[b * FF + f] = __float2half_rn(p);
        }
    }
    __syncthreads();
}

__global__ void __launch_bounds__(NTHR, 1) s2s_kernel(
    const float* __restrict__ x_seq,
    const float* __restrict__ Wih_e, const float* __restrict__ Whh_e,
    const float* __restrict__ bih_e, const float* __restrict__ bhh_e,
    const float* __restrict__ Wih_d, const float* __restrict__ Whh_d,
    const float* __restrict__ bih_d, const float* __restrict__ bhh_d,
    const float* __restrict__ Wfc, const float* __restrict__ bfc,
    const int* __restrict__ plen,
    float* __restrict__ out)
{
    extern __shared__ char dsm[];
    const int tid = threadIdx.x;
    const int m0 = (blockIdx.x >> 6) * MB;        // 2 batch blocks
    const int n0 = (blockIdx.x & 63) * NH;        // 64 hidden blocks

    // Phase 0: resident encoder weights (per-CTA) + global x->fp16, h/c zero
    load_weights((__half*)dsm, Whh_e, Wih_e, n0);
    {
        const int gtid = blockIdx.x * NTHR + tid;
        const int gstr = NCTA * NTHR;
        for (int i = gtid; i < BB * SS * FF / 4; i += gstr) {
            float4 v = ((const float4*)x_seq)[i];
            ((__half2*)g_xs)[i * 2]     = __floats2half2_rn(v.x, v.y);
            ((__half2*)g_xs)[i * 2 + 1] = __floats2half2_rn(v.z, v.w);
        }
        uint4 z4 = make_uint4(0, 0, 0, 0);
        for (int i = gtid; i < BB * HH / 8; i += gstr)
            ((uint4*)g_h[0])[i] = z4;
        float4 zf = make_float4(0.f, 0.f, 0.f, 0.f);
        for (int i = gtid; i < BB * HH / 4; i += gstr)
            ((float4*)g_c)[i] = zf;
    }
    grid_barrier();

    int cur = 0;
    // ---- encoder ----
    for (int t = 0; t < SS; t++) {
        lstm_step(dsm, g_h[cur], g_h[cur ^ 1], g_c, bih_e, bhh_e,
                  g_xs + (size_t)t * FF, SS * FF, m0, n0);
        grid_barrier();
        cur ^= 1;
    }

    // swap to decoder weights (per-CTA smem, only local sync needed)
    __syncthreads();
    load_weights((__half*)dsm, Whh_d, Wih_d, n0);
    __syncthreads();

    // ---- decoder ----
    const int T = *plen;
    for (int t = 0; t < T; t++) {
        const __half* xp = (t == 0) ? (g_xs + (size_t)(SS - 1) * FF) : g_x;
        const int xs = (t == 0) ? (SS * FF) : FF;
        lstm_step(dsm, g_h[cur], g_h[cur ^ 1], g_c, bih_d, bhh_d,
                  xp, xs, m0, n0);
        grid_barrier();
        cur ^= 1;
        pred_step(dsm, g_h[cur], Wfc, bfc, out, t, T);
        grid_barrier();
    }
}

extern "C" void kernel_launch(void* const* d_in, const int* in_sizes, int n_in,
                              void* d_out, int out_size)
{
    const float* x_seq = (const float*)d_in[0];
    const float* Wih_e = (const float*)d_in[1];
    const float* Whh_e = (const float*)d_in[2];
    const float* bih_e = (const float*)d_in[3];
    const float* bhh_e = (const float*)d_in[4];
    const float* Wih_d = (const float*)d_in[5];
    const float* Whh_d = (const float*)d_in[6];
    const float* bih_d = (const float*)d_in[7];
    const float* bhh_d = (const float*)d_in[8];
    const float* Wfc   = (const float*)d_in[9];
    const float* bfc   = (const float*)d_in[10];
    const int*   plen  = (const int*)d_in[11];
    float* out = (float*)d_out;

    cudaFuncSetAttribute(s2s_kernel,
                         cudaFuncAttributeMaxDynamicSharedMemorySize, SMEM_BYTES);
    s2s_kernel<<<NCTA, NTHR, SMEM_BYTES>>>(x_seq, Wih_e, Whh_e, bih_e, bhh_e,
                                           Wih_d, Whh_d, bih_d, bhh_d,
                                           Wfc, bfc, plen, out);
}

// round 7
// speedup vs baseline: 6.4990x; 1.0072x over previous
#include <cuda_runtime.h>
#include <cuda_fp16.h>
#include <cstdint>

// Shapes (fixed)
#define BB 256
#define SS 512
#define FF 64
#define HH 1024

#define NCTA 128    // 2 batch-blocks x 64 hidden-blocks
#define NTHR 512    // 16 warps: 4m x 2n x 2k-split
#define MB 128      // batch rows per CTA
#define NH 16       // hidden cols per CTA
#define GT 64       // gate rows per CTA = 4*NH
#define KC 64       // K chunk (four k16 mma sub-steps; 2 per k-warp)
#define KTOT (HH + FF)          // 1088
#define NCHUNK (KTOT / KC)      // 17
#define NSTG 4

#define WST 1096    // weight smem row stride (halves); conflict-free ldsm
#define AST 72      // A smem row stride (halves); conflict-free ldsm
#define GST 68

#define WBYTES (GT * WST * 2)           // 140288
#define ASTG_BYTES (MB * AST * 2)       // 18432
#define SMEM_BYTES (WBYTES + NSTG * ASTG_BYTES)   // 214016

// Persistent state (no allocations allowed)
__device__ __half g_h[2][BB * HH];
__device__ float  g_c[BB * HH];
__device__ __half g_x[BB * FF];
__device__ __half g_xs[BB * SS * FF];
__device__ unsigned g_bar_cnt;
__device__ unsigned g_bar_gen;

__device__ __forceinline__ void grid_barrier() {
    __syncthreads();
    if (threadIdx.x == 0) {
        __threadfence();
        unsigned gen = *(volatile unsigned*)&g_bar_gen;
        if (atomicAdd(&g_bar_cnt, 1u) == NCTA - 1u) {
            atomicExch(&g_bar_cnt, 0u);
            __threadfence();
            atomicAdd(&g_bar_gen, 1u);
        } else {
            while (*(volatile unsigned*)&g_bar_gen == gen) { }
        }
        __threadfence();
    }
    __syncthreads();
}

__device__ __forceinline__ float sigm(float x) {
    return 1.0f / (1.0f + __expf(-x));
}
__device__ __forceinline__ float tanh_f(float x) {
    float xx = fminf(fmaxf(x, -15.0f), 15.0f);
    float e = __expf(2.0f * xx);
    return (e - 1.0f) / (e + 1.0f);
}
__device__ __forceinline__ void cpa16(uint32_t s, const void* g) {
    asm volatile("cp.async.cg.shared.global [%0], [%1], 16;" :: "r"(s), "l"(g));
}
__device__ __forceinline__ void ldsm4(uint32_t r[4], uint32_t a) {
    asm volatile("ldmatrix.sync.aligned.m8n8.x4.shared.b16 {%0,%1,%2,%3}, [%4];"
                 : "=r"(r[0]), "=r"(r[1]), "=r"(r[2]), "=r"(r[3]) : "r"(a));
}
__device__ __forceinline__ void mmaH(float d[4], const uint32_t a[4],
                                     uint32_t b0, uint32_t b1) {
    asm volatile("mma.sync.aligned.m16n8k16.row.col.f32.f16.f16.f32 "
                 "{%0,%1,%2,%3},{%4,%5,%6,%7},{%8,%9},{%0,%1,%2,%3};"
                 : "+f"(d[0]), "+f"(d[1]), "+f"(d[2]), "+f"(d[3])
                 : "r"(a[0]), "r"(a[1]), "r"(a[2]), "r"(a[3]),
                   "r"(b0), "r"(b1));
}

// Load this CTA's gate-row weight slice (fp16) into resident smem.
__device__ void load_weights(__half* W, const float* __restrict__ Whh,
                             const float* __restrict__ Wih, int n0) {
    const int tid = threadIdx.x;
    for (int idx = tid; idx < GT * KTOT; idx += NTHR) {
        int row = idx / KTOT;
        int k = idx - row * KTOT;
        int g = row >> 4, hid = n0 + (row & 15);
        float v = (k < HH) ? Whh[(size_t)(g * HH + hid) * HH + k]
                           : Wih[(size_t)(g * HH + hid) * FF + (k - HH)];
        W[row * WST + k] = __float2half_rn(v);
    }
}

// One LSTM step for this CTA's (MB x NH) tile. Weights resident in smem.
// 16 warps: kw = warp>>3 splits the 4 k16 sub-steps of each chunk (2 each).
__device__ __forceinline__ void lstm_step(
    char* dsm,
    const __half* __restrict__ hcur, __half* __restrict__ hnext,
    float* __restrict__ cbuf,
    const float* __restrict__ bih, const float* __restrict__ bhh,
    const __half* __restrict__ xptr, int xstride,
    int m0, int n0)
{
    const int tid = threadIdx.x;
    const int lane = tid & 31, warp = tid >> 5;
    const int kw = warp >> 3;                 // 0/1: k-split half
    const int wm = ((warp >> 1) & 3) * 32;    // 4 m groups
    const int wn = (warp & 1) * 32;           // 2 gate-col groups

    const uint32_t base = (uint32_t)__cvta_generic_to_shared(dsm);
    const uint32_t Wbase = base;
    const uint32_t Abase = base + (uint32_t)WBYTES;

    // ---- A loader: 128 rows x 8 segs of 16B per chunk; 2 cp.async/thread ----
    int lrow[2], lseg[2];
    const __half* hrow[2];
    const __half* xrow[2];
#pragma unroll
    for (int q = 0; q < 2; q++) {
        int idx = tid + q * NTHR;
        lrow[q] = idx >> 3;
        lseg[q] = idx & 7;
        hrow[q] = hcur + (size_t)(m0 + lrow[q]) * HH + lseg[q] * 8;
        xrow[q] = xptr + (size_t)(m0 + lrow[q]) * xstride + lseg[q] * 8;
    }
    auto issue = [&](int ci) {
        const uint32_t so = (uint32_t)((ci & (NSTG - 1)) * ASTG_BYTES);
        const int k0 = ci * KC;
#pragma unroll
        for (int q = 0; q < 2; q++) {
            uint32_t dst = Abase + so + (uint32_t)(lrow[q] * (AST * 2) + lseg[q] * 16);
            if (k0 < HH) cpa16(dst, hrow[q] + k0);
            else         cpa16(dst, xrow[q] + (k0 - HH));
        }
        asm volatile("cp.async.commit_group;" ::: "memory");
    };

    // ---- ldmatrix lane addressing ----
    const int lr = lane & 7, lt = lane >> 3;
    const int madd = (lt & 1) * 8;       // tiles 1,3: +8 rows
    const int kq = (lt >> 1) * 8;        // tiles 2,3: +8 halves in k
    const uint32_t aA0 = Abase + (uint32_t)(((wm + lr + madd) * AST + kq) * 2);
    const uint32_t aA1 = aA0 + (uint32_t)(16 * AST * 2);
    const uint32_t bB0 = Wbase + (uint32_t)(((wn + lr + madd) * WST + kq) * 2);
    const uint32_t bB1 = bB0 + (uint32_t)(16 * WST * 2);

    float acc[2][4][4];
#pragma unroll
    for (int mi = 0; mi < 2; mi++)
#pragma unroll
        for (int ni = 0; ni < 4; ni++)
#pragma unroll
            for (int q = 0; q < 4; q++) acc[mi][ni][q] = 0.0f;

    issue(0); issue(1); issue(2);

#pragma unroll 1
    for (int i = 0; i < NCHUNK; i++) {
        if (i + 3 >= NCHUNK)
            asm volatile("cp.async.commit_group;" ::: "memory");
        asm volatile("cp.async.wait_group 2;" ::: "memory");
        __syncthreads();
        if (i + 3 < NCHUNK) issue(i + 3);

        const uint32_t so = (uint32_t)((i & (NSTG - 1)) * ASTG_BYTES);
        const uint32_t ko = (uint32_t)(i * KC * 2);   // weight k offset (bytes)
        // this k-warp's two k16 sub-steps: kb = kw*2 + {0,1}
#pragma unroll
        for (int kb2 = 0; kb2 < 2; kb2++) {
            const int kb = kw * 2 + kb2;
            uint32_t A0[4], A1[4], B0[4], B1[4];
            ldsm4(A0, aA0 + so + kb * 32);
            ldsm4(A1, aA1 + so + kb * 32);
            ldsm4(B0, bB0 + ko + kb * 32);
            ldsm4(B1, bB1 + ko + kb * 32);
            mmaH(acc[0][0], A0, B0[0], B0[2]);
            mmaH(acc[0][1], A0, B0[1], B0[3]);
            mmaH(acc[0][2], A0, B1[0], B1[2]);
            mmaH(acc[0][3], A0, B1[1], B1[3]);
            mmaH(acc[1][0], A1, B0[0], B0[2]);
            mmaH(acc[1][1], A1, B0[1], B0[3]);
            mmaH(acc[1][2], A1, B1[0], B1[2]);
            mmaH(acc[1][3], A1, B1[1], B1[3]);
        }
    }

    // epilogue: k-split merge in Gs (overlay A staging region)
    asm volatile("cp.async.wait_group 0;" ::: "memory");
    __syncthreads();
    float (*Gs)[GST] = (float (*)[GST])(dsm + WBYTES);
    if (kw == 0) {
#pragma unroll
        for (int mi = 0; mi < 2; mi++)
#pragma unroll
            for (int ni = 0; ni < 4; ni++) {
                int r = wm + mi * 16 + (lane >> 2);
                int c = wn + ni * 8 + (lane & 3) * 2;
                *(float2*)&Gs[r][c]     = make_float2(acc[mi][ni][0], acc[mi][ni][1]);
                *(float2*)&Gs[r + 8][c] = make_float2(acc[mi][ni][2], acc[mi][ni][3]);
            }
    }
    __syncthreads();
    if (kw == 1) {
#pragma unroll
        for (int mi = 0; mi < 2; mi++)
#pragma unroll
            for (int ni = 0; ni < 4; ni++) {
                int r = wm + mi * 16 + (lane >> 2);
                int c = wn + ni * 8 + (lane & 3) * 2;
                float2 p0 = *(const float2*)&Gs[r][c];
                float2 p1 = *(const float2*)&Gs[r + 8][c];
                *(float2*)&Gs[r][c] =
                    make_float2(p0.x + acc[mi][ni][0], p0.y + acc[mi][ni][1]);
                *(float2*)&Gs[r + 8][c] =
                    make_float2(p1.x + acc[mi][ni][2], p1.y + acc[mi][ni][3]);
            }
    }
    __syncthreads();

    // pointwise LSTM update (2048 elems, 4 per thread)
    const int hid = tid & 15;
    const int rb = tid >> 4;      // 0..31
    const float bi = bih[0 * HH + n0 + hid] + bhh[0 * HH + n0 + hid];
    const float bf = bih[1 * HH + n0 + hid] + bhh[1 * HH + n0 + hid];
    const float bg = bih[2 * HH + n0 + hid] + bhh[2 * HH + n0 + hid];
    const float bo = bih[3 * HH + n0 + hid] + bhh[3 * HH + n0 + hid];
#pragma unroll
    for (int it = 0; it < (MB * NH) / NTHR; it++) {
        int r = rb + it * 32;
        float iv = Gs[r][hid]      + bi;
        float fv = Gs[r][16 + hid] + bf;
        float gv = Gs[r][32 + hid] + bg;
        float ov = Gs[r][48 + hid] + bo;
        int gi = (m0 + r) * HH + n0 + hid;
        float cold = cbuf[gi];
        float cn = sigm(fv) * cold + sigm(iv) * tanh_f(gv);
        float hn = sigm(ov) * tanh_f(cn);
        cbuf[gi] = cn;
        hnext[gi] = __float2half_rn(hn);
    }
}

// pred = h @ W_fc^T + b_fc ; out[b,t,:] fp32, g_x fp16 feed.
__device__ __forceinline__ void pred_step(
    char* dsm, const __half* __restrict__ h,
    const float* __restrict__ Wfc, const float* __restrict__ bfc,
    float* __restrict__ out, int t, int T)
{
    float (*Hs)[HH] = (float (*)[HH])(dsm + WBYTES);
    const int tid = threadIdx.x;
    const int pr0 = blockIdx.x * 2;

    // stage 2 h rows (half -> float): 1024 half2, 2 per thread
#pragma unroll
    for (int q = 0; q < 2; q++) {
        int idx = tid + q * NTHR;
        int r = idx >> 9;
        int c2 = idx & 511;
        float2 f = __half22float2(((const __half2*)(h + (size_t)(pr0 + r) * HH))[c2]);
        Hs[r][c2 * 2]     = f.x;
        Hs[r][c2 * 2 + 1] = f.y;
    }
    __syncthreads();

    const int warp = tid >> 5, lane = tid & 31;
    for (int oi = warp; oi < 128; oi += 16) {
        int r = oi >> 6;
        int f = oi & 63;
        const float4* wrow = (const float4*)&Wfc[(size_t)f * HH];
        const float4* hrow = (const float4*)&Hs[r][0];
        float s = 0.0f;
#pragma unroll 4
        for (int k4 = lane; k4 < 256; k4 += 32) {
            float4 w = wrow[k4];
            float4 hv = hrow[k4];
            s += w.x * hv.x + w.y * hv.y + w.z * hv.z + w.w * hv.w;
        }
#pragma unroll
        for (int off = 16; off; off >>= 1)
            s += __shfl_xor_sync(0xffffffffu, s, off);
        if (lane == 0) {
            float p = s + bfc[f];
            int b = pr0 + r;
            out[(size_t)b * T * FF + t * FF + f] = p;
            g_x[b * FF + f] = __float2half_rn(p);
        }
    }
    __syncthreads();
}

__global__ void __launch_bounds__(NTHR, 1) s2s_kernel(
    const float* __restrict__ x_seq,
    const float* __restrict__ Wih_e, const float* __restrict__ Whh_e,
    const float* __restrict__ bih_e, const float* __restrict__ bhh_e,
    const float* __restrict__ Wih_d, const float* __restrict__ Whh_d,
    const float* __restrict__ bih_d, const float* __restrict__ bhh_d,
    const float* __restrict__ Wfc, const float* __restrict__ bfc,
    const int* __restrict__ plen,
    float* __restrict__ out)
{
    extern __shared__ char dsm[];
    const int tid = threadIdx.x;
    const int m0 = (blockIdx.x >> 6) * MB;        // 2 batch blocks
    const int n0 = (blockIdx.x & 63) * NH;        // 64 hidden blocks

    // Phase 0: resident encoder weights (per-CTA) + global x->fp16, h/c zero
    load_weights((__half*)dsm, Whh_e, Wih_e, n0);
    {
        const int gtid = blockIdx.x * NTHR + tid;
        const int gstr = NCTA * NTHR;
        for (int i = gtid; i < BB * SS * FF / 4; i += gstr) {
            float4 v = ((const float4*)x_seq)[i];
            ((__half2*)g_xs)[i * 2]     = __floats2half2_rn(v.x, v.y);
            ((__half2*)g_xs)[i * 2 + 1] = __floats2half2_rn(v.z, v.w);
        }
        uint4 z4 = make_uint4(0, 0, 0, 0);
        for (int i = gtid; i < BB * HH / 8; i += gstr)
            ((uint4*)g_h[0])[i] = z4;
        float4 zf = make_float4(0.f, 0.f, 0.f, 0.f);
        for (int i = gtid; i < BB * HH / 4; i += gstr)
            ((float4*)g_c)[i] = zf;
    }
    grid_barrier();

    int cur = 0;
    // ---- encoder ----
    for (int t = 0; t < SS; t++) {
        lstm_step(dsm, g_h[cur], g_h[cur ^ 1], g_c, bih_e, bhh_e,
                  g_xs + (size_t)t * FF, SS * FF, m0, n0);
        grid_barrier();
        cur ^= 1;
    }

    // swap to decoder weights (per-CTA smem, only local sync needed)
    __syncthreads();
    load_weights((__half*)dsm, Whh_d, Wih_d, n0);
    __syncthreads();

    // ---- decoder ----
    const int T = *plen;
    for (int t = 0; t < T; t++) {
        const __half* xp = (t == 0) ? (g_xs + (size_t)(SS - 1) * FF) : g_x;
        const int xs = (t == 0) ? (SS * FF) : FF;
        lstm_step(dsm, g_h[cur], g_h[cur ^ 1], g_c, bih_d, bhh_d,
                  xp, xs, m0, n0);
        grid_barrier();
        cur ^= 1;
        pred_step(dsm, g_h[cur], Wfc, bfc, out, t, T);
        grid_barrier();
    }
}

extern "C" void kernel_launch(void* const* d_in, const int* in_sizes, int n_in,
                              void* d_out, int out_size)
{
    const float* x_seq = (const float*)d_in[0];
    const float* Wih_e = (const float*)d_in[1];
    const float* Whh_e = (const float*)d_in[2];
    const float* bih_e = (const float*)d_in[3];
    const float* bhh_e = (const float*)d_in[4];
    const float* Wih_d = (const float*)d_in[5];
    const float* Whh_d = (const float*)d_in[6];
    const float* bih_d = (const float*)d_in[7];
    const float* bhh_d = (const float*)d_in[8];
    const float* Wfc   = (const float*)d_in[9];
    const float* bfc   = (const float*)d_in[10];
    const int*   plen  = (const int*)d_in[11];
    float* out = (float*)d_out;

    cudaFuncSetAttribute(s2s_kernel,
                         cudaFuncAttributeMaxDynamicSharedMemorySize, SMEM_BYTES);
    s2s_kernel<<<NCTA, NTHR, SMEM_BYTES>>>(x_seq, Wih_e, Whh_e, bih_e, bhh_e,
                                           Wih_d, Whh_d, bih_d, bhh_d,
                                           Wfc, bfc, plen, out);
}

// round 9
// speedup vs baseline: 6.6607x; 1.0249x over previous
#include <cuda_runtime.h>
#include <cuda_fp16.h>
#include <cstdint>

// Shapes (fixed)
#define BB 256
#define SS 512
#define FF 64
#define HH 1024

#define NCTA 128    // 2 batch-groups x 64 hidden-blocks
#define NTHR 512    // 16 warps: 4 m-groups x (2n x 2k-split)
#define MB 128      // batch rows per CTA
#define NH 16       // hidden cols per CTA
#define GT 64       // gate rows per CTA = 4*NH
#define KC 64       // K chunk
#define KTOT (HH + FF)          // 1088
#define NCHUNK (KTOT / KC)      // 17
#define NSTG 3      // per-group A slots (triple buffer)

#define WST 1096    // weight smem row stride (halves); conflict-free ldsm
#define GST 68

#define WBYTES (GT * WST * 2)           // 140288
#define ASLOT 4608                      // 32 rows x 144B (72-half stride)
#define AGRP (NSTG * ASLOT)             // 13824 per m-group
#define ABYTES (4 * AGRP)               // 55296
#define AOFF WBYTES
#define CTRL (WBYTES + ABYTES)          // 195584
#define SMEM_BYTES (CTRL + 256)

// Persistent state (no allocations allowed)
__device__ __half g_h[2][BB * HH];
__device__ float  g_c[BB * HH];
__device__ __half g_x[BB * FF];
__device__ __half g_xs[BB * SS * FF];
__device__ unsigned g_bar_cnt[2];
__device__ unsigned g_bar_gen[2];

// two-group grid barrier (batch halves are fully independent)
__device__ __forceinline__ void grid_barrier(int grp) {
    __syncthreads();
    if (threadIdx.x == 0) {
        __threadfence();
        unsigned gen = *(volatile unsigned*)&g_bar_gen[grp];
        if (atomicAdd(&g_bar_cnt[grp], 1u) == 63u) {
            atomicExch(&g_bar_cnt[grp], 0u);
            __threadfence();
            atomicAdd(&g_bar_gen[grp], 1u);
        } else {
            while (*(volatile unsigned*)&g_bar_gen[grp] == gen) { }
        }
        __threadfence();
    }
    __syncthreads();
}

__device__ __forceinline__ float sigm(float x) { return 1.0f / (1.0f + __expf(-x)); }
__device__ __forceinline__ float tanh_f(float x) {
    float xx = fminf(fmaxf(x, -15.0f), 15.0f);
    float e = __expf(2.0f * xx);
    return (e - 1.0f) / (e + 1.0f);
}
__device__ __forceinline__ void cpa16(uint32_t s, const void* g) {
    asm volatile("cp.async.cg.shared.global [%0], [%1], 16;" :: "r"(s), "l"(g));
}
#define CP_COMMIT() asm volatile("cp.async.commit_group;" ::: "memory")
__device__ __forceinline__ void ldsm4(uint32_t r[4], uint32_t a) {
    asm volatile("ldmatrix.sync.aligned.m8n8.x4.shared.b16 {%0,%1,%2,%3}, [%4];"
                 : "=r"(r[0]), "=r"(r[1]), "=r"(r[2]), "=r"(r[3]) : "r"(a));
}
__device__ __forceinline__ void mmaH(float d[4], const uint32_t a[4],
                                     uint32_t b0, uint32_t b1) {
    asm volatile("mma.sync.aligned.m16n8k16.row.col.f32.f16.f16.f32 "
                 "{%0,%1,%2,%3},{%4,%5,%6,%7},{%8,%9},{%0,%1,%2,%3};"
                 : "+f"(d[0]), "+f"(d[1]), "+f"(d[2]), "+f"(d[3])
                 : "r"(a[0]), "r"(a[1]), "r"(a[2]), "r"(a[3]),
                   "r"(b0), "r"(b1));
}

// Load this CTA's gate-row weight slice (fp16) into resident smem.
__device__ void load_weights(__half* W, const float* __restrict__ Whh,
                             const float* __restrict__ Wih, int n0) {
    const int tid = threadIdx.x;
    for (int idx = tid; idx < GT * KTOT; idx += NTHR) {
        int row = idx / KTOT;
        int k = idx - row * KTOT;
        int g = row >> 4, hid = n0 + (row & 15);
        float v = (k < HH) ? Whh[(size_t)(g * HH + hid) * HH + k]
                           : Wih[(size_t)(g * HH + hid) * FF + (k - HH)];
        W[row * WST + k] = __float2half_rn(v);
    }
}

// One LSTM step. Per-m-group private A slots + named-barrier sync:
// no CTA-wide barrier inside the 17-chunk loop.
__device__ __forceinline__ void lstm_step(
    char* dsm,
    const __half* __restrict__ hcur, __half* __restrict__ hnext,
    float* __restrict__ cbuf, const float* __restrict__ sbias,
    const __half* __restrict__ xptr, int xstride,
    int m0, int n0)
{
    const int tid = threadIdx.x;
    const int lane = tid & 31, warp = tid >> 5;
    const int kw = warp >> 3;                 // 0/1: k-split half
    const int wm = (warp >> 1) & 3;           // m-group 0..3
    const int wn = warp & 1;                  // gate-col half
    const int barid = 1 + wm;                 // named barrier per m-group

    const uint32_t base = (uint32_t)__cvta_generic_to_shared(dsm);
    const uint32_t Wbase = base;
    const uint32_t Agrp = base + (uint32_t)(AOFF + wm * AGRP);

    // ---- loader: this warp's quarter of the group's 32x64 tile ----
    // quarter q in 0..3; seg ids q*64 + lane*2 + {0,1}; row=id>>3, ks=id&7
    const int q = (warp & 1) | ((warp >> 3) << 1);
    const int id0 = q * 64 + lane * 2;
    const int row0 = id0 >> 3, ks0 = id0 & 7;
    const int row1 = (id0 + 1) >> 3, ks1 = (id0 + 1) & 7;
    const __half* h0 = hcur + (size_t)(m0 + wm * 32 + row0) * HH + ks0 * 8;
    const __half* h1 = hcur + (size_t)(m0 + wm * 32 + row1) * HH + ks1 * 8;
    const __half* x0 = xptr + (size_t)(m0 + wm * 32 + row0) * xstride + ks0 * 8;
    const __half* x1 = xptr + (size_t)(m0 + wm * 32 + row1) * xstride + ks1 * 8;
    const uint32_t d0 = (uint32_t)(row0 * 144 + ks0 * 16);
    const uint32_t d1 = (uint32_t)(row1 * 144 + ks1 * 16);

    auto issue = [&](int ci) {
        uint32_t sb = Agrp + (uint32_t)((ci % NSTG) * ASLOT);
        int k0 = ci * KC;
        if (k0 < HH) {
            cpa16(sb + d0, h0 + k0);
            cpa16(sb + d1, h1 + k0);
        } else {
            cpa16(sb + d0, x0 + (k0 - HH));
            cpa16(sb + d1, x1 + (k0 - HH));
        }
        CP_COMMIT();
    };

    // ---- ldmatrix lane addressing ----
    const int lr = lane & 7, lt = lane >> 3;
    const int madd = (lt & 1) * 8;            // tiles 1,3: +8 rows
    const uint32_t aA0 = (uint32_t)((lr + madd) * 144 + (lt >> 1) * 16); // slot-rel
    const uint32_t aA1 = aA0 + (uint32_t)(16 * 144);
    const uint32_t bB0 = Wbase
        + (uint32_t)(((wn * 32 + lr + madd) * WST + (lt >> 1) * 8) * 2);
    const uint32_t bB1 = bB0 + (uint32_t)(16 * WST * 2);

    float acc[2][4][4];
#pragma unroll
    for (int mi = 0; mi < 2; mi++)
#pragma unroll
        for (int ni = 0; ni < 4; ni++)
#pragma unroll
            for (int p = 0; p < 4; p++) acc[mi][ni][p] = 0.0f;

    issue(0); issue(1);

#pragma unroll 1
    for (int i = 0; i < NCHUNK; i++) {
        if (i + 2 >= NCHUNK) CP_COMMIT();   // keep group accounting advancing
        asm volatile("cp.async.wait_group 1;" ::: "memory");
        asm volatile("bar.sync %0, 128;" :: "r"(barid) : "memory");
        if (i + 2 < NCHUNK) issue(i + 2);

        const uint32_t sA = Agrp + (uint32_t)((i % NSTG) * ASLOT);
        const uint32_t ko = (uint32_t)(i * (KC * 2));  // weight k offset (bytes)
#pragma unroll
        for (int kb2 = 0; kb2 < 2; kb2++) {
            const int kb = kw * 2 + kb2;
            uint32_t A0[4], A1[4], B0[4], B1[4];
            ldsm4(A0, sA + aA0 + kb * 32);
            ldsm4(A1, sA + aA1 + kb * 32);
            ldsm4(B0, bB0 + ko + kb * 32);
            ldsm4(B1, bB1 + ko + kb * 32);
            mmaH(acc[0][0], A0, B0[0], B0[2]);
            mmaH(acc[0][1], A0, B0[1], B0[3]);
            mmaH(acc[0][2], A0, B1[0], B1[2]);
            mmaH(acc[0][3], A0, B1[1], B1[3]);
            mmaH(acc[1][0], A1, B0[0], B0[2]);
            mmaH(acc[1][1], A1, B0[1], B0[3]);
            mmaH(acc[1][2], A1, B1[0], B1[2]);
            mmaH(acc[1][3], A1, B1[1], B1[3]);
        }
    }

    // epilogue: k-split merge in Gs (overlays A region)
    asm volatile("cp.async.wait_group 0;" ::: "memory");
    __syncthreads();
    float (*Gs)[GST] = (float (*)[GST])(dsm + AOFF);
    const int wmB = wm * 32;
    const int wnB = wn * 32;
    if (kw == 0) {
#pragma unroll
        for (int mi = 0; mi < 2; mi++)
#pragma unroll
            for (int ni = 0; ni < 4; ni++) {
                int r = wmB + mi * 16 + (lane >> 2);
                int c = wnB + ni * 8 + (lane & 3) * 2;
                *(float2*)&Gs[r][c]     = make_float2(acc[mi][ni][0], acc[mi][ni][1]);
                *(float2*)&Gs[r + 8][c] = make_float2(acc[mi][ni][2], acc[mi][ni][3]);
            }
    }
    __syncthreads();
    if (kw == 1) {
#pragma unroll
        for (int mi = 0; mi < 2; mi++)
#pragma unroll
            for (int ni = 0; ni < 4; ni++) {
                int r = wmB + mi * 16 + (lane >> 2);
                int c = wnB + ni * 8 + (lane & 3) * 2;
                float2 p0 = *(const float2*)&Gs[r][c];
                float2 p1 = *(const float2*)&Gs[r + 8][c];
                *(float2*)&Gs[r][c] =
                    make_float2(p0.x + acc[mi][ni][0], p0.y + acc[mi][ni][1]);
                *(float2*)&Gs[r + 8][c] =
                    make_float2(p1.x + acc[mi][ni][2], p1.y + acc[mi][ni][3]);
            }
    }
    __syncthreads();

    // pointwise LSTM update (2048 elems, 4 per thread)
    const int hid = tid & 15;
    const int rb = tid >> 4;      // 0..31
    const float bi = sbias[hid];
    const float bf = sbias[16 + hid];
    const float bg = sbias[32 + hid];
    const float bo = sbias[48 + hid];
#pragma unroll
    for (int it = 0; it < (MB * NH) / NTHR; it++) {
        int r = rb + it * 32;
        float iv = Gs[r][hid]      + bi;
        float fv = Gs[r][16 + hid] + bf;
        float gv = Gs[r][32 + hid] + bg;
        float ov = Gs[r][48 + hid] + bo;
        int gi = (m0 + r) * HH + n0 + hid;
        float cold = cbuf[gi];
        float cn = sigm(fv) * cold + sigm(iv) * tanh_f(gv);
        float hn = sigm(ov) * tanh_f(cn);
        cbuf[gi] = cn;
        hnext[gi] = __float2half_rn(hn);
    }
}

// pred = h @ W_fc^T + b_fc ; out[b,t,:] fp32, g_x fp16 feed.
__device__ __forceinline__ void pred_step(
    char* dsm, const __half* __restrict__ h,
    const float* __restrict__ Wfc, const float* __restrict__ bfc,
    float* __restrict__ out, int t, int T)
{
    float (*Hs)[HH] = (float (*)[HH])(dsm + AOFF);
    const int tid = threadIdx.x;
    const int pr0 = blockIdx.x * 2;

#pragma unroll
    for (int q = 0; q < 2; q++) {
        int idx = tid + q * NTHR;
        int r = idx >> 9, c2 = idx & 511;
        float2 f = __half22float2(((const __half2*)(h + (size_t)(pr0 + r) * HH))[c2]);
        Hs[r][c2 * 2]     = f.x;
        Hs[r][c2 * 2 + 1] = f.y;
    }
    __syncthreads();

    const int warp = tid >> 5, lane = tid & 31;
    for (int oi = warp; oi < 128; oi += 16) {
        int r = oi >> 6, f = oi & 63;
        const float4* wrow = (const float4*)&Wfc[(size_t)f * HH];
        const float4* hrow = (const float4*)&Hs[r][0];
        float s = 0.0f;
#pragma unroll 4
        for (int k4 = lane; k4 < 256; k4 += 32) {
            float4 w = wrow[k4];
            float4 hv = hrow[k4];
            s += w.x * hv.x + w.y * hv.y + w.z * hv.z + w.w * hv.w;
        }
#pragma unroll
        for (int off = 16; off; off >>= 1)
            s += __shfl_xor_sync(0xffffffffu, s, off);
        if (lane == 0) {
            float p = s + bfc[f];
            int b = pr0 + r;
            out[(size_t)b * T * FF + t * FF + f] = p;
            g_x[b * FF + f] = __float2half_rn(p);
        }
    }
    __syncthreads();
}

__global__ void __launch_bounds__(NTHR, 1) s2s_kernel(
    const float* __restrict__ x_seq,
    const float* __restrict__ Wih_e, const float* __restrict__ Whh_e,
    const float* __restrict__ bih_e, const float* __restrict__ bhh_e,
    const float* __restrict__ Wih_d, const float* __restrict__ Whh_d,
    const float* __restrict__ bih_d, const float* __restrict__ bhh_d,
    const float* __restrict__ Wfc, const float* __restrict__ bfc,
    const int* __restrict__ plen,
    float* __restrict__ out)
{
    extern __shared__ char dsm[];
    const int tid = threadIdx.x;
    const int gb = blockIdx.x >> 6;               // batch group 0/1
    const int m0 = gb * MB;
    const int n0 = (blockIdx.x & 63) * NH;
    float* sbias = (float*)(dsm + CTRL);

    // Phase 0: encoder weights + biases + group-local x conv / h,c zero
    load_weights((__half*)dsm, Whh_e, Wih_e, n0);
    if (tid < 64)
        sbias[tid] = bih_e[(tid >> 4) * HH + n0 + (tid & 15)]
                   + bhh_e[(tid >> 4) * HH + n0 + (tid & 15)];
    {
        const int gtid = (blockIdx.x & 63) * NTHR + tid;
        const int gstr = 64 * NTHR;
        const int n4 = MB * SS * FF / 4;
        const int xb4 = gb * n4;
        for (int i = gtid; i < n4; i += gstr) {
            float4 v = ((const float4*)x_seq)[xb4 + i];
            ((__half2*)g_xs)[(xb4 + i) * 2]     = __floats2half2_rn(v.x, v.y);
            ((__half2*)g_xs)[(xb4 + i) * 2 + 1] = __floats2half2_rn(v.z, v.w);
        }
        uint4 z4 = make_uint4(0, 0, 0, 0);
        const int hb = gb * (MB * HH / 8);
        for (int i = gtid; i < MB * HH / 8; i += gstr) ((uint4*)g_h[0])[hb + i] = z4;
        float4 zf = make_float4(0.f, 0.f, 0.f, 0.f);
        const int cbx = gb * (MB * HH / 4);
        for (int i = gtid; i < MB * HH / 4; i += gstr) ((float4*)g_c)[cbx + i] = zf;
    }
    grid_barrier(gb);

    int cur = 0;
    // ---- encoder ----
#pragma unroll 1
    for (int t = 0; t < SS; t++) {
        lstm_step(dsm, g_h[cur], g_h[cur ^ 1], g_c, sbias,
                  g_xs + (size_t)t * FF, SS * FF, m0, n0);
        grid_barrier(gb);
        cur ^= 1;
    }

    // swap to decoder weights (per-CTA smem, local sync only)
    __syncthreads();
    load_weights((__half*)dsm, Whh_d, Wih_d, n0);
    if (tid < 64)
        sbias[tid] = bih_d[(tid >> 4) * HH + n0 + (tid & 15)]
                   + bhh_d[(tid >> 4) * HH + n0 + (tid & 15)];
    __syncthreads();

    // ---- decoder ----
    const int T = *plen;
#pragma unroll 1
    for (int t = 0; t < T; t++) {
        const __half* xp = (t == 0) ? (g_xs + (size_t)(SS - 1) * FF) : g_x;
        const int xs = (t == 0) ? (SS * FF) : FF;
        lstm_step(dsm, g_h[cur], g_h[cur ^ 1], g_c, sbias,
                  xp, xs, m0, n0);
        grid_barrier(gb);
        cur ^= 1;
        pred_step(dsm, g_h[cur], Wfc, bfc, out, t, T);
        grid_barrier(gb);
    }
}

extern "C" void kernel_launch(void* const* d_in, const int* in_sizes, int n_in,
                              void* d_out, int out_size)
{
    const float* x_seq = (const float*)d_in[0];
    const float* Wih_e = (const float*)d_in[1];
    const float* Whh_e = (const float*)d_in[2];
    const float* bih_e = (const float*)d_in[3];
    const float* bhh_e = (const float*)d_in[4];
    const float* Wih_d = (const float*)d_in[5];
    const float* Whh_d = (const float*)d_in[6];
    const float* bih_d = (const float*)d_in[7];
    const float* bhh_d = (const float*)d_in[8];
    const float* Wfc   = (const float*)d_in[9];
    const float* bfc   = (const float*)d_in[10];
    const int*   plen  = (const int*)d_in[11];
    float* out = (float*)d_out;

    cudaFuncSetAttribute(s2s_kernel,
                         cudaFuncAttributeMaxDynamicSharedMemorySize, SMEM_BYTES);
    s2s_kernel<<<NCTA, NTHR, SMEM_BYTES>>>(x_seq, Wih_e, Whh_e, bih_e, bhh_e,
                                           Wih_d, Whh_d, bih_d, bhh_d,
                                           Wfc, bfc, plen, out);
}